// round 1
// baseline (speedup 1.0000x reference)
#include <cuda_runtime.h>
#include <math.h>

#define Dm   1024
#define Sm   2048
#define Bm   2
#define Hm   16
#define HDm  64
#define FCm  4096
#define ROWS (Bm*Sm)        /* 4096 */
#define EPSm 1e-5f

// Scratch (no cudaMalloc allowed)
__device__ float g_h1  [(size_t)ROWS*Dm];       // 16 MB
__device__ float g_qkv [(size_t)ROWS*3*Dm];     // 48 MB
__device__ float g_attn[(size_t)ROWS*Dm];       // 16 MB
__device__ float g_h2  [(size_t)ROWS*Dm];       // 16 MB
__device__ float g_mlp [(size_t)ROWS*FCm];      // 64 MB

// ---------------------------------------------------------------------------
// LayerNorm: one block per row, 256 threads, D=1024 (4 elems/thread, in regs)
// ---------------------------------------------------------------------------
__global__ __launch_bounds__(256) void ln_kernel(
    const float* __restrict__ x, const float* __restrict__ g,
    const float* __restrict__ b, float* __restrict__ y)
{
    int row = blockIdx.x;
    int t = threadIdx.x;
    const float* xr = x + (size_t)row * Dm;
    float v[4];
#pragma unroll
    for (int i = 0; i < 4; i++) v[i] = xr[t + i*256];

    __shared__ float red[8];
    // mean
    float s = v[0] + v[1] + v[2] + v[3];
#pragma unroll
    for (int o = 16; o > 0; o >>= 1) s += __shfl_xor_sync(0xffffffffu, s, o);
    if ((t & 31) == 0) red[t >> 5] = s;
    __syncthreads();
    float mu;
    {
        float z = red[t & 7];
        // all threads read all 8; just sum serially via shared (cheap)
        float tot = red[0]+red[1]+red[2]+red[3]+red[4]+red[5]+red[6]+red[7];
        (void)z;
        mu = tot * (1.0f / Dm);
    }
    __syncthreads();
    // variance (two-pass, values in regs)
    float q = 0.f;
#pragma unroll
    for (int i = 0; i < 4; i++) { float d0 = v[i] - mu; q += d0*d0; }
#pragma unroll
    for (int o = 16; o > 0; o >>= 1) q += __shfl_xor_sync(0xffffffffu, q, o);
    if ((t & 31) == 0) red[t >> 5] = q;
    __syncthreads();
    float var = (red[0]+red[1]+red[2]+red[3]+red[4]+red[5]+red[6]+red[7]) * (1.0f / Dm);
    float rstd = rsqrtf(var + EPSm);

    float* yr = y + (size_t)row * Dm;
#pragma unroll
    for (int i = 0; i < 4; i++) {
        int c = t + i*256;
        yr[c] = (v[i] - mu) * rstd * g[c] + b[c];
    }
}

// ---------------------------------------------------------------------------
// SGEMM: C[M,N] = A[M,K] @ B[K,N] + bias[N] (+relu) (+res[M,N])
// 128x128 block tile, 8x8 thread tile, BK=8, 256 threads.
// All M,N,K here are multiples of the tile sizes — no bounds checks.
// ---------------------------------------------------------------------------
__global__ __launch_bounds__(256) void sgemm_kernel(
    const float* __restrict__ A, const float* __restrict__ B,
    const float* __restrict__ bias, const float* __restrict__ res,
    float* __restrict__ C, int M, int N, int K, int relu)
{
    const int BK = 8;
    __shared__ float As[BK][128];
    __shared__ float Bs[BK][128];

    int tid  = threadIdx.x;
    int row0 = blockIdx.y * 128;
    int col0 = blockIdx.x * 128;

    int arow = tid >> 1;          // 0..127
    int acol = (tid & 1) * 4;     // 0 or 4
    int brow = tid >> 5;          // 0..7
    int bcol = (tid & 31) * 4;    // 0..124

    int tx = (tid % 16) * 8;
    int ty = (tid / 16) * 8;

    float acc[8][8];
#pragma unroll
    for (int i = 0; i < 8; i++)
#pragma unroll
        for (int j = 0; j < 8; j++) acc[i][j] = 0.f;

    for (int k0 = 0; k0 < K; k0 += BK) {
        float4 a4 = *(const float4*)(A + (size_t)(row0 + arow) * K + k0 + acol);
        As[acol + 0][arow] = a4.x;
        As[acol + 1][arow] = a4.y;
        As[acol + 2][arow] = a4.z;
        As[acol + 3][arow] = a4.w;
        float4 b4 = *(const float4*)(B + (size_t)(k0 + brow) * N + col0 + bcol);
        *(float4*)&Bs[brow][bcol] = b4;
        __syncthreads();

#pragma unroll
        for (int k = 0; k < BK; k++) {
            float ra[8], rb[8];
#pragma unroll
            for (int i = 0; i < 8; i++) ra[i] = As[k][ty + i];
#pragma unroll
            for (int j = 0; j < 8; j++) rb[j] = Bs[k][tx + j];
#pragma unroll
            for (int i = 0; i < 8; i++)
#pragma unroll
                for (int j = 0; j < 8; j++)
                    acc[i][j] += ra[i] * rb[j];
        }
        __syncthreads();
    }

#pragma unroll
    for (int i = 0; i < 8; i++) {
        int r = row0 + ty + i;
#pragma unroll
        for (int j = 0; j < 8; j += 4) {
            int c = col0 + tx + j;
            float4 o;
            o.x = acc[i][j + 0] + bias[c + 0];
            o.y = acc[i][j + 1] + bias[c + 1];
            o.z = acc[i][j + 2] + bias[c + 2];
            o.w = acc[i][j + 3] + bias[c + 3];
            if (relu) {
                o.x = fmaxf(o.x, 0.f); o.y = fmaxf(o.y, 0.f);
                o.z = fmaxf(o.z, 0.f); o.w = fmaxf(o.w, 0.f);
            }
            if (res) {
                const float4 r4 = *(const float4*)(res + (size_t)r * N + c);
                o.x += r4.x; o.y += r4.y; o.z += r4.z; o.w += r4.w;
            }
            *(float4*)(C + (size_t)r * N + c) = o;
        }
    }
}

// ---------------------------------------------------------------------------
// Flash-style attention: block = 128 threads = 128 q-rows of one (b,h).
// K/V staged through smem in tiles of 32 keys; online softmax per thread.
// Writes attn_out = softmax(QK^T/sqrt(hd)) @ V + x  (residual fused).
// ---------------------------------------------------------------------------
__global__ __launch_bounds__(128) void attn_kernel(
    const float* __restrict__ qkv, const float* __restrict__ x,
    float* __restrict__ attn)
{
    int h = blockIdx.y;
    int b = blockIdx.z;
    int t = threadIdx.x;
    int qrow = b * Sm + blockIdx.x * 128 + t;

    const float* qptr = qkv + (size_t)qrow * (3 * Dm) + h * HDm;
    float qreg[HDm];
#pragma unroll
    for (int d = 0; d < HDm; d++) qreg[d] = qptr[d];

    const float scale = 0.125f;  // 1/sqrt(64)
    float acc[HDm];
#pragma unroll
    for (int d = 0; d < HDm; d++) acc[d] = 0.f;
    float mmax = -1e30f, lsum = 0.f;

    __shared__ float Ksh[32][HDm];
    __shared__ float Vsh[32][HDm];

    for (int kk = 0; kk < Sm; kk += 32) {
        // cooperative load of 32 keys + 32 values (float4, coalesced)
#pragma unroll
        for (int i = 0; i < 4; i++) {
            int fi = t + i * 128;         // 0..511 float4 slots
            int kr = fi >> 4;             // key row in tile
            int dc = (fi & 15) * 4;       // dim offset
            size_t base = (size_t)(b * Sm + kk + kr) * (3 * Dm) + h * HDm + dc;
            *(float4*)&Ksh[kr][dc] = *(const float4*)(qkv + base + Dm);
            *(float4*)&Vsh[kr][dc] = *(const float4*)(qkv + base + 2 * Dm);
        }
        __syncthreads();

        float p[32];
        float tmax = mmax;
#pragma unroll
        for (int j = 0; j < 32; j++) {
            float s = 0.f;
#pragma unroll
            for (int d = 0; d < HDm; d++) s += qreg[d] * Ksh[j][d];
            s *= scale;
            p[j] = s;
            tmax = fmaxf(tmax, s);
        }
        float corr = __expf(mmax - tmax);
        mmax = tmax;
        lsum *= corr;
#pragma unroll
        for (int d = 0; d < HDm; d++) acc[d] *= corr;
#pragma unroll
        for (int j = 0; j < 32; j++) {
            float e = __expf(p[j] - mmax);
            lsum += e;
#pragma unroll
            for (int d = 0; d < HDm; d++) acc[d] += e * Vsh[j][d];
        }
        __syncthreads();
    }

    float inv = 1.0f / lsum;
    size_t obase = (size_t)qrow * Dm + h * HDm;
#pragma unroll
    for (int d = 0; d < HDm; d++)
        attn[obase + d] = acc[d] * inv + x[obase + d];
}

// ---------------------------------------------------------------------------
// Launch
// ---------------------------------------------------------------------------
extern "C" void kernel_launch(void* const* d_in, const int* in_sizes, int n_in,
                              void* d_out, int out_size)
{
    const float* x     = (const float*)d_in[0];
    const float* ln1_g = (const float*)d_in[1];
    const float* ln1_b = (const float*)d_in[2];
    const float* w_qkv = (const float*)d_in[3];
    const float* b_qkv = (const float*)d_in[4];
    const float* ln2_g = (const float*)d_in[5];
    const float* ln2_b = (const float*)d_in[6];
    const float* w1    = (const float*)d_in[7];
    const float* b1    = (const float*)d_in[8];
    const float* w2    = (const float*)d_in[9];
    const float* b2    = (const float*)d_in[10];
    float* out = (float*)d_out;

    float *h1, *qkv, *attn, *h2, *mlp;
    cudaGetSymbolAddress((void**)&h1,   g_h1);
    cudaGetSymbolAddress((void**)&qkv,  g_qkv);
    cudaGetSymbolAddress((void**)&attn, g_attn);
    cudaGetSymbolAddress((void**)&h2,   g_h2);
    cudaGetSymbolAddress((void**)&mlp,  g_mlp);

    // 1. LN1
    ln_kernel<<<ROWS, 256>>>(x, ln1_g, ln1_b, h1);
    // 2. QKV = h1 @ w_qkv + b_qkv      [4096,1024]x[1024,3072]
    sgemm_kernel<<<dim3(3*Dm/128, ROWS/128), 256>>>(h1, w_qkv, b_qkv, nullptr,
                                                    qkv, ROWS, 3*Dm, Dm, 0);
    // 3. attention + residual
    attn_kernel<<<dim3(Sm/128, Hm, Bm), 128>>>(qkv, x, attn);
    // 4. LN2
    ln_kernel<<<ROWS, 256>>>(attn, ln2_g, ln2_b, h2);
    // 5. m = relu(h2 @ w1 + b1)        [4096,1024]x[1024,4096]
    sgemm_kernel<<<dim3(FCm/128, ROWS/128), 256>>>(h2, w1, b1, nullptr,
                                                   mlp, ROWS, FCm, Dm, 1);
    // 6. out = m @ w2 + b2 + attn      [4096,4096]x[4096,1024]
    sgemm_kernel<<<dim3(Dm/128, ROWS/128), 256>>>(mlp, w2, b2, attn,
                                                  out, ROWS, Dm, FCm, 0);
}

// round 2
// speedup vs baseline: 1.4465x; 1.4465x over previous
#include <cuda_runtime.h>
#include <math.h>
#include <stdint.h>

#define Dm   1024
#define Sm   2048
#define Bm   2
#define Hm   16
#define HDm  64
#define FCm  4096
#define ROWS (Bm*Sm)        /* 4096 */
#define EPSm 1e-5f

// Scratch (no cudaMalloc allowed)
__device__ float g_h1  [(size_t)ROWS*Dm];       // 16 MB
__device__ float g_qkv [(size_t)ROWS*3*Dm];     // 48 MB
__device__ float g_attn[(size_t)ROWS*Dm];       // 16 MB
__device__ float g_h2  [(size_t)ROWS*Dm];       // 16 MB
__device__ float g_mlp [(size_t)ROWS*FCm];      // 64 MB

// ---------------------------------------------------------------------------
// LayerNorm: one block per row, 256 threads, D=1024 (4 elems/thread, in regs)
// ---------------------------------------------------------------------------
__global__ __launch_bounds__(256) void ln_kernel(
    const float* __restrict__ x, const float* __restrict__ g,
    const float* __restrict__ b, float* __restrict__ y)
{
    int row = blockIdx.x;
    int t = threadIdx.x;
    const float* xr = x + (size_t)row * Dm;
    float v[4];
#pragma unroll
    for (int i = 0; i < 4; i++) v[i] = xr[t + i*256];

    __shared__ float red[8];
    float s = v[0] + v[1] + v[2] + v[3];
#pragma unroll
    for (int o = 16; o > 0; o >>= 1) s += __shfl_xor_sync(0xffffffffu, s, o);
    if ((t & 31) == 0) red[t >> 5] = s;
    __syncthreads();
    float mu = (red[0]+red[1]+red[2]+red[3]+red[4]+red[5]+red[6]+red[7]) * (1.0f / Dm);
    __syncthreads();
    float q = 0.f;
#pragma unroll
    for (int i = 0; i < 4; i++) { float d0 = v[i] - mu; q += d0*d0; }
#pragma unroll
    for (int o = 16; o > 0; o >>= 1) q += __shfl_xor_sync(0xffffffffu, q, o);
    if ((t & 31) == 0) red[t >> 5] = q;
    __syncthreads();
    float var = (red[0]+red[1]+red[2]+red[3]+red[4]+red[5]+red[6]+red[7]) * (1.0f / Dm);
    float rstd = rsqrtf(var + EPSm);

    float* yr = y + (size_t)row * Dm;
#pragma unroll
    for (int i = 0; i < 4; i++) {
        int c = t + i*256;
        yr[c] = (v[i] - mu) * rstd * g[c] + b[c];
    }
}

// ---------------------------------------------------------------------------
// TF32 tensor-core GEMM: C[M,N] = A[M,K] @ B[K,N] + bias (+relu) (+res)
// Block 128x128x32, 256 threads (8 warps), warp tile 64x32,
// mma.sync.aligned.m16n8k8.row.col.f32.tf32.tf32.f32
// smem layout: As[k][m], Bs[k][n], row stride 132 floats.
// ---------------------------------------------------------------------------
__device__ __forceinline__ uint32_t f2tf32(float x) {
    uint32_t r;
    asm("cvt.rna.tf32.f32 %0, %1;" : "=r"(r) : "f"(x));
    return r;
}

__device__ __forceinline__ void mma_tf32(float c[4],
    uint32_t a0, uint32_t a1, uint32_t a2, uint32_t a3,
    uint32_t b0, uint32_t b1)
{
    asm volatile(
        "mma.sync.aligned.m16n8k8.row.col.f32.tf32.tf32.f32 "
        "{%0,%1,%2,%3}, {%4,%5,%6,%7}, {%8,%9}, {%0,%1,%2,%3};"
        : "+f"(c[0]), "+f"(c[1]), "+f"(c[2]), "+f"(c[3])
        : "r"(a0), "r"(a1), "r"(a2), "r"(a3), "r"(b0), "r"(b1));
}

#define TSTRIDE 132

__global__ __launch_bounds__(256) void tgemm_kernel(
    const float* __restrict__ A, const float* __restrict__ B,
    const float* __restrict__ bias, const float* __restrict__ res,
    float* __restrict__ C, int M, int N, int K, int relu)
{
    __shared__ uint32_t As[32][TSTRIDE];   // [k][m]
    __shared__ uint32_t Bs[32][TSTRIDE];   // [k][n]

    int tid  = threadIdx.x;
    int wid  = tid >> 5;
    int lane = tid & 31;
    int grp  = lane >> 2;     // 0..7
    int thr  = lane & 3;      // 0..3
    int warp_m = (wid >> 2) * 64;   // 0 or 64
    int warp_n = (wid & 3) * 32;    // 0..96
    int row0 = blockIdx.y * 128;
    int col0 = blockIdx.x * 128;

    float acc[4][4][4];
#pragma unroll
    for (int mi = 0; mi < 4; mi++)
#pragma unroll
        for (int ni = 0; ni < 4; ni++)
#pragma unroll
            for (int f = 0; f < 4; f++) acc[mi][ni][f] = 0.f;

    // global-load index precompute
    for (int k0 = 0; k0 < K; k0 += 32) {
        // A tile: 128 rows x 32 k, transpose into As[k][m]
#pragma unroll
        for (int i = 0; i < 4; i++) {
            int fi = tid + i * 256;
            int r  = fi >> 3;            // 0..127
            int kq = (fi & 7) * 4;       // 0,4,...,28
            float4 a4 = *(const float4*)(A + (size_t)(row0 + r) * K + k0 + kq);
            As[kq + 0][r] = f2tf32(a4.x);
            As[kq + 1][r] = f2tf32(a4.y);
            As[kq + 2][r] = f2tf32(a4.z);
            As[kq + 3][r] = f2tf32(a4.w);
        }
        // B tile: 32 k x 128 cols, direct into Bs[k][n]
#pragma unroll
        for (int i = 0; i < 4; i++) {
            int fi = tid + i * 256;
            int kr = fi >> 5;            // 0..31
            int nc = (fi & 31) * 4;      // 0..124
            float4 b4 = *(const float4*)(B + (size_t)(k0 + kr) * N + col0 + nc);
            uint4 u;
            u.x = f2tf32(b4.x); u.y = f2tf32(b4.y);
            u.z = f2tf32(b4.z); u.w = f2tf32(b4.w);
            *(uint4*)&Bs[kr][nc] = u;
        }
        __syncthreads();

#pragma unroll
        for (int k8 = 0; k8 < 32; k8 += 8) {
            uint32_t af[4][4], bf[4][2];
#pragma unroll
            for (int mi = 0; mi < 4; mi++) {
                int m = warp_m + mi * 16;
                af[mi][0] = As[k8 + thr    ][m + grp    ];
                af[mi][1] = As[k8 + thr    ][m + grp + 8];
                af[mi][2] = As[k8 + thr + 4][m + grp    ];
                af[mi][3] = As[k8 + thr + 4][m + grp + 8];
            }
#pragma unroll
            for (int ni = 0; ni < 4; ni++) {
                int n = warp_n + ni * 8;
                bf[ni][0] = Bs[k8 + thr    ][n + grp];
                bf[ni][1] = Bs[k8 + thr + 4][n + grp];
            }
#pragma unroll
            for (int mi = 0; mi < 4; mi++)
#pragma unroll
                for (int ni = 0; ni < 4; ni++)
                    mma_tf32(acc[mi][ni],
                             af[mi][0], af[mi][1], af[mi][2], af[mi][3],
                             bf[ni][0], bf[ni][1]);
        }
        __syncthreads();
    }

    // Epilogue: c0,c1 -> (r, c),(r, c+1); c2,c3 -> (r+8, c),(r+8, c+1)
#pragma unroll
    for (int mi = 0; mi < 4; mi++) {
#pragma unroll
        for (int ni = 0; ni < 4; ni++) {
            int r = row0 + warp_m + mi * 16 + grp;
            int c = col0 + warp_n + ni * 8 + 2 * thr;
            float b0 = bias[c], b1 = bias[c + 1];
            float o0 = acc[mi][ni][0] + b0;
            float o1 = acc[mi][ni][1] + b1;
            float o2 = acc[mi][ni][2] + b0;
            float o3 = acc[mi][ni][3] + b1;
            if (relu) {
                o0 = fmaxf(o0, 0.f); o1 = fmaxf(o1, 0.f);
                o2 = fmaxf(o2, 0.f); o3 = fmaxf(o3, 0.f);
            }
            if (res) {
                const float2 r0 = *(const float2*)(res + (size_t)r * N + c);
                const float2 r1 = *(const float2*)(res + (size_t)(r + 8) * N + c);
                o0 += r0.x; o1 += r0.y; o2 += r1.x; o3 += r1.y;
            }
            *(float2*)(C + (size_t)r * N + c)       = make_float2(o0, o1);
            *(float2*)(C + (size_t)(r + 8) * N + c) = make_float2(o2, o3);
        }
    }
}

// ---------------------------------------------------------------------------
// Flash-style attention (unchanged): 128 threads = 128 q-rows of one (b,h).
// ---------------------------------------------------------------------------
__global__ __launch_bounds__(128) void attn_kernel(
    const float* __restrict__ qkv, const float* __restrict__ x,
    float* __restrict__ attn)
{
    int h = blockIdx.y;
    int b = blockIdx.z;
    int t = threadIdx.x;
    int qrow = b * Sm + blockIdx.x * 128 + t;

    const float* qptr = qkv + (size_t)qrow * (3 * Dm) + h * HDm;
    float qreg[HDm];
#pragma unroll
    for (int d = 0; d < HDm; d++) qreg[d] = qptr[d];

    const float scale = 0.125f;
    float acc[HDm];
#pragma unroll
    for (int d = 0; d < HDm; d++) acc[d] = 0.f;
    float mmax = -1e30f, lsum = 0.f;

    __shared__ float Ksh[32][HDm];
    __shared__ float Vsh[32][HDm];

    for (int kk = 0; kk < Sm; kk += 32) {
#pragma unroll
        for (int i = 0; i < 4; i++) {
            int fi = t + i * 128;
            int kr = fi >> 4;
            int dc = (fi & 15) * 4;
            size_t base = (size_t)(b * Sm + kk + kr) * (3 * Dm) + h * HDm + dc;
            *(float4*)&Ksh[kr][dc] = *(const float4*)(qkv + base + Dm);
            *(float4*)&Vsh[kr][dc] = *(const float4*)(qkv + base + 2 * Dm);
        }
        __syncthreads();

        float p[32];
        float tmax = mmax;
#pragma unroll
        for (int j = 0; j < 32; j++) {
            float s = 0.f;
#pragma unroll
            for (int d = 0; d < HDm; d++) s += qreg[d] * Ksh[j][d];
            s *= scale;
            p[j] = s;
            tmax = fmaxf(tmax, s);
        }
        float corr = __expf(mmax - tmax);
        mmax = tmax;
        lsum *= corr;
#pragma unroll
        for (int d = 0; d < HDm; d++) acc[d] *= corr;
#pragma unroll
        for (int j = 0; j < 32; j++) {
            float e = __expf(p[j] - mmax);
            lsum += e;
#pragma unroll
            for (int d = 0; d < HDm; d++) acc[d] += e * Vsh[j][d];
        }
        __syncthreads();
    }

    float inv = 1.0f / lsum;
    size_t obase = (size_t)qrow * Dm + h * HDm;
#pragma unroll
    for (int d = 0; d < HDm; d++)
        attn[obase + d] = acc[d] * inv + x[obase + d];
}

// ---------------------------------------------------------------------------
// Launch
// ---------------------------------------------------------------------------
extern "C" void kernel_launch(void* const* d_in, const int* in_sizes, int n_in,
                              void* d_out, int out_size)
{
    const float* x     = (const float*)d_in[0];
    const float* ln1_g = (const float*)d_in[1];
    const float* ln1_b = (const float*)d_in[2];
    const float* w_qkv = (const float*)d_in[3];
    const float* b_qkv = (const float*)d_in[4];
    const float* ln2_g = (const float*)d_in[5];
    const float* ln2_b = (const float*)d_in[6];
    const float* w1    = (const float*)d_in[7];
    const float* b1    = (const float*)d_in[8];
    const float* w2    = (const float*)d_in[9];
    const float* b2    = (const float*)d_in[10];
    float* out = (float*)d_out;

    float *h1, *qkv, *attn, *h2, *mlp;
    cudaGetSymbolAddress((void**)&h1,   g_h1);
    cudaGetSymbolAddress((void**)&qkv,  g_qkv);
    cudaGetSymbolAddress((void**)&attn, g_attn);
    cudaGetSymbolAddress((void**)&h2,   g_h2);
    cudaGetSymbolAddress((void**)&mlp,  g_mlp);

    // 1. LN1
    ln_kernel<<<ROWS, 256>>>(x, ln1_g, ln1_b, h1);
    // 2. QKV = h1 @ w_qkv + b_qkv      [4096,1024]x[1024,3072]
    tgemm_kernel<<<dim3(3*Dm/128, ROWS/128), 256>>>(h1, w_qkv, b_qkv, nullptr,
                                                    qkv, ROWS, 3*Dm, Dm, 0);
    // 3. attention + residual
    attn_kernel<<<dim3(Sm/128, Hm, Bm), 128>>>(qkv, x, attn);
    // 4. LN2
    ln_kernel<<<ROWS, 256>>>(attn, ln2_g, ln2_b, h2);
    // 5. m = relu(h2 @ w1 + b1)        [4096,1024]x[1024,4096]
    tgemm_kernel<<<dim3(FCm/128, ROWS/128), 256>>>(h2, w1, b1, nullptr,
                                                   mlp, ROWS, FCm, Dm, 1);
    // 6. out = m @ w2 + b2 + attn      [4096,4096]x[4096,1024]
    tgemm_kernel<<<dim3(Dm/128, ROWS/128), 256>>>(mlp, w2, b2, attn,
                                                  out, ROWS, Dm, FCm, 0);
}

// round 3
// speedup vs baseline: 1.4790x; 1.0225x over previous
#include <cuda_runtime.h>
#include <math.h>
#include <stdint.h>

#define Dm   1024
#define Sm   2048
#define Bm   2
#define Hm   16
#define HDm  64
#define FCm  4096
#define ROWS (Bm*Sm)        /* 4096 */
#define EPSm 1e-5f

// Scratch (no cudaMalloc allowed)
__device__ float g_h1  [(size_t)ROWS*Dm];       // 16 MB
__device__ float g_qkv [(size_t)ROWS*3*Dm];     // 48 MB
__device__ float g_attn[(size_t)ROWS*Dm];       // 16 MB
__device__ float g_h2  [(size_t)ROWS*Dm];       // 16 MB
__device__ float g_mlp [(size_t)ROWS*FCm];      // 64 MB

// ---------------------------------------------------------------------------
// LayerNorm: one block per row, 256 threads, D=1024 (4 elems/thread, in regs)
// ---------------------------------------------------------------------------
__global__ __launch_bounds__(256) void ln_kernel(
    const float* __restrict__ x, const float* __restrict__ g,
    const float* __restrict__ b, float* __restrict__ y)
{
    int row = blockIdx.x;
    int t = threadIdx.x;
    const float* xr = x + (size_t)row * Dm;
    float v[4];
#pragma unroll
    for (int i = 0; i < 4; i++) v[i] = xr[t + i*256];

    __shared__ float red[8];
    float s = v[0] + v[1] + v[2] + v[3];
#pragma unroll
    for (int o = 16; o > 0; o >>= 1) s += __shfl_xor_sync(0xffffffffu, s, o);
    if ((t & 31) == 0) red[t >> 5] = s;
    __syncthreads();
    float mu = (red[0]+red[1]+red[2]+red[3]+red[4]+red[5]+red[6]+red[7]) * (1.0f / Dm);
    __syncthreads();
    float q = 0.f;
#pragma unroll
    for (int i = 0; i < 4; i++) { float d0 = v[i] - mu; q += d0*d0; }
#pragma unroll
    for (int o = 16; o > 0; o >>= 1) q += __shfl_xor_sync(0xffffffffu, q, o);
    if ((t & 31) == 0) red[t >> 5] = q;
    __syncthreads();
    float var = (red[0]+red[1]+red[2]+red[3]+red[4]+red[5]+red[6]+red[7]) * (1.0f / Dm);
    float rstd = rsqrtf(var + EPSm);

    float* yr = y + (size_t)row * Dm;
#pragma unroll
    for (int i = 0; i < 4; i++) {
        int c = t + i*256;
        yr[c] = (v[i] - mu) * rstd * g[c] + b[c];
    }
}

// ---------------------------------------------------------------------------
// TF32 tensor-core GEMM: C[M,N] = A[M,K] @ B[K,N] + bias (+relu) (+res)
// Block 128x128x32, 256 threads (8 warps), warp tile 64x32,
// mma.sync.aligned.m16n8k8.row.col.f32.tf32.tf32.f32
// smem layout: As[k][m], Bs[k][n], row stride 132 floats.
// ---------------------------------------------------------------------------
__device__ __forceinline__ uint32_t f2tf32(float x) {
    uint32_t r;
    asm("cvt.rna.tf32.f32 %0, %1;" : "=r"(r) : "f"(x));
    return r;
}

__device__ __forceinline__ void mma_tf32(float c[4],
    uint32_t a0, uint32_t a1, uint32_t a2, uint32_t a3,
    uint32_t b0, uint32_t b1)
{
    asm volatile(
        "mma.sync.aligned.m16n8k8.row.col.f32.tf32.tf32.f32 "
        "{%0,%1,%2,%3}, {%4,%5,%6,%7}, {%8,%9}, {%0,%1,%2,%3};"
        : "+f"(c[0]), "+f"(c[1]), "+f"(c[2]), "+f"(c[3])
        : "r"(a0), "r"(a1), "r"(a2), "r"(a3), "r"(b0), "r"(b1));
}

#define TSTRIDE 132

__global__ __launch_bounds__(256) void tgemm_kernel(
    const float* __restrict__ A, const float* __restrict__ B,
    const float* __restrict__ bias, const float* __restrict__ res,
    float* __restrict__ C, int M, int N, int K, int relu)
{
    __shared__ uint32_t As[32][TSTRIDE];   // [k][m]
    __shared__ uint32_t Bs[32][TSTRIDE];   // [k][n]

    int tid  = threadIdx.x;
    int wid  = tid >> 5;
    int lane = tid & 31;
    int grp  = lane >> 2;     // 0..7
    int thr  = lane & 3;      // 0..3
    int warp_m = (wid >> 2) * 64;   // 0 or 64
    int warp_n = (wid & 3) * 32;    // 0..96
    int row0 = blockIdx.y * 128;
    int col0 = blockIdx.x * 128;

    float acc[4][4][4];
#pragma unroll
    for (int mi = 0; mi < 4; mi++)
#pragma unroll
        for (int ni = 0; ni < 4; ni++)
#pragma unroll
            for (int f = 0; f < 4; f++) acc[mi][ni][f] = 0.f;

    // global-load index precompute
    for (int k0 = 0; k0 < K; k0 += 32) {
        // A tile: 128 rows x 32 k, transpose into As[k][m]
#pragma unroll
        for (int i = 0; i < 4; i++) {
            int fi = tid + i * 256;
            int r  = fi >> 3;            // 0..127
            int kq = (fi & 7) * 4;       // 0,4,...,28
            float4 a4 = *(const float4*)(A + (size_t)(row0 + r) * K + k0 + kq);
            As[kq + 0][r] = f2tf32(a4.x);
            As[kq + 1][r] = f2tf32(a4.y);
            As[kq + 2][r] = f2tf32(a4.z);
            As[kq + 3][r] = f2tf32(a4.w);
        }
        // B tile: 32 k x 128 cols, direct into Bs[k][n]
#pragma unroll
        for (int i = 0; i < 4; i++) {
            int fi = tid + i * 256;
            int kr = fi >> 5;            // 0..31
            int nc = (fi & 31) * 4;      // 0..124
            float4 b4 = *(const float4*)(B + (size_t)(k0 + kr) * N + col0 + nc);
            uint4 u;
            u.x = f2tf32(b4.x); u.y = f2tf32(b4.y);
            u.z = f2tf32(b4.z); u.w = f2tf32(b4.w);
            *(uint4*)&Bs[kr][nc] = u;
        }
        __syncthreads();

#pragma unroll
        for (int k8 = 0; k8 < 32; k8 += 8) {
            uint32_t af[4][4], bf[4][2];
#pragma unroll
            for (int mi = 0; mi < 4; mi++) {
                int m = warp_m + mi * 16;
                af[mi][0] = As[k8 + thr    ][m + grp    ];
                af[mi][1] = As[k8 + thr    ][m + grp + 8];
                af[mi][2] = As[k8 + thr + 4][m + grp    ];
                af[mi][3] = As[k8 + thr + 4][m + grp + 8];
            }
#pragma unroll
            for (int ni = 0; ni < 4; ni++) {
                int n = warp_n + ni * 8;
                bf[ni][0] = Bs[k8 + thr    ][n + grp];
                bf[ni][1] = Bs[k8 + thr + 4][n + grp];
            }
#pragma unroll
            for (int mi = 0; mi < 4; mi++)
#pragma unroll
                for (int ni = 0; ni < 4; ni++)
                    mma_tf32(acc[mi][ni],
                             af[mi][0], af[mi][1], af[mi][2], af[mi][3],
                             bf[ni][0], bf[ni][1]);
        }
        __syncthreads();
    }

    // Epilogue: c0,c1 -> (r, c),(r, c+1); c2,c3 -> (r+8, c),(r+8, c+1)
#pragma unroll
    for (int mi = 0; mi < 4; mi++) {
#pragma unroll
        for (int ni = 0; ni < 4; ni++) {
            int r = row0 + warp_m + mi * 16 + grp;
            int c = col0 + warp_n + ni * 8 + 2 * thr;
            float b0 = bias[c], b1 = bias[c + 1];
            float o0 = acc[mi][ni][0] + b0;
            float o1 = acc[mi][ni][1] + b1;
            float o2 = acc[mi][ni][2] + b0;
            float o3 = acc[mi][ni][3] + b1;
            if (relu) {
                o0 = fmaxf(o0, 0.f); o1 = fmaxf(o1, 0.f);
                o2 = fmaxf(o2, 0.f); o3 = fmaxf(o3, 0.f);
            }
            if (res) {
                const float2 r0 = *(const float2*)(res + (size_t)r * N + c);
                const float2 r1 = *(const float2*)(res + (size_t)(r + 8) * N + c);
                o0 += r0.x; o1 += r0.y; o2 += r1.x; o3 += r1.y;
            }
            *(float2*)(C + (size_t)r * N + c)       = make_float2(o0, o1);
            *(float2*)(C + (size_t)(r + 8) * N + c) = make_float2(o2, o3);
        }
    }
}

// ---------------------------------------------------------------------------
// Flash-style attention (unchanged): 128 threads = 128 q-rows of one (b,h).
// ---------------------------------------------------------------------------
__global__ __launch_bounds__(128) void attn_kernel(
    const float* __restrict__ qkv, const float* __restrict__ x,
    float* __restrict__ attn)
{
    int h = blockIdx.y;
    int b = blockIdx.z;
    int t = threadIdx.x;
    int qrow = b * Sm + blockIdx.x * 128 + t;

    const float* qptr = qkv + (size_t)qrow * (3 * Dm) + h * HDm;
    float qreg[HDm];
#pragma unroll
    for (int d = 0; d < HDm; d++) qreg[d] = qptr[d];

    const float scale = 0.125f;
    float acc[HDm];
#pragma unroll
    for (int d = 0; d < HDm; d++) acc[d] = 0.f;
    float mmax = -1e30f, lsum = 0.f;

    __shared__ float Ksh[32][HDm];
    __shared__ float Vsh[32][HDm];

    for (int kk = 0; kk < Sm; kk += 32) {
#pragma unroll
        for (int i = 0; i < 4; i++) {
            int fi = t + i * 128;
            int kr = fi >> 4;
            int dc = (fi & 15) * 4;
            size_t base = (size_t)(b * Sm + kk + kr) * (3 * Dm) + h * HDm + dc;
            *(float4*)&Ksh[kr][dc] = *(const float4*)(qkv + base + Dm);
            *(float4*)&Vsh[kr][dc] = *(const float4*)(qkv + base + 2 * Dm);
        }
        __syncthreads();

        float p[32];
        float tmax = mmax;
#pragma unroll
        for (int j = 0; j < 32; j++) {
            float s = 0.f;
#pragma unroll
            for (int d = 0; d < HDm; d++) s += qreg[d] * Ksh[j][d];
            s *= scale;
            p[j] = s;
            tmax = fmaxf(tmax, s);
        }
        float corr = __expf(mmax - tmax);
        mmax = tmax;
        lsum *= corr;
#pragma unroll
        for (int d = 0; d < HDm; d++) acc[d] *= corr;
#pragma unroll
        for (int j = 0; j < 32; j++) {
            float e = __expf(p[j] - mmax);
            lsum += e;
#pragma unroll
            for (int d = 0; d < HDm; d++) acc[d] += e * Vsh[j][d];
        }
        __syncthreads();
    }

    float inv = 1.0f / lsum;
    size_t obase = (size_t)qrow * Dm + h * HDm;
#pragma unroll
    for (int d = 0; d < HDm; d++)
        attn[obase + d] = acc[d] * inv + x[obase + d];
}

// ---------------------------------------------------------------------------
// Launch
// ---------------------------------------------------------------------------
extern "C" void kernel_launch(void* const* d_in, const int* in_sizes, int n_in,
                              void* d_out, int out_size)
{
    const float* x     = (const float*)d_in[0];
    const float* ln1_g = (const float*)d_in[1];
    const float* ln1_b = (const float*)d_in[2];
    const float* w_qkv = (const float*)d_in[3];
    const float* b_qkv = (const float*)d_in[4];
    const float* ln2_g = (const float*)d_in[5];
    const float* ln2_b = (const float*)d_in[6];
    const float* w1    = (const float*)d_in[7];
    const float* b1    = (const float*)d_in[8];
    const float* w2    = (const float*)d_in[9];
    const float* b2    = (const float*)d_in[10];
    float* out = (float*)d_out;

    float *h1, *qkv, *attn, *h2, *mlp;
    cudaGetSymbolAddress((void**)&h1,   g_h1);
    cudaGetSymbolAddress((void**)&qkv,  g_qkv);
    cudaGetSymbolAddress((void**)&attn, g_attn);
    cudaGetSymbolAddress((void**)&h2,   g_h2);
    cudaGetSymbolAddress((void**)&mlp,  g_mlp);

    // 1. LN1
    ln_kernel<<<ROWS, 256>>>(x, ln1_g, ln1_b, h1);
    // 2. QKV = h1 @ w_qkv + b_qkv      [4096,1024]x[1024,3072]
    tgemm_kernel<<<dim3(3*Dm/128, ROWS/128), 256>>>(h1, w_qkv, b_qkv, nullptr,
                                                    qkv, ROWS, 3*Dm, Dm, 0);
    // 3. attention + residual
    attn_kernel<<<dim3(Sm/128, Hm, Bm), 128>>>(qkv, x, attn);
    // 4. LN2
    ln_kernel<<<ROWS, 256>>>(attn, ln2_g, ln2_b, h2);
    // 5. m = relu(h2 @ w1 + b1)        [4096,1024]x[1024,4096]
    tgemm_kernel<<<dim3(FCm/128, ROWS/128), 256>>>(h2, w1, b1, nullptr,
                                                   mlp, ROWS, FCm, Dm, 1);
    // 6. out = m @ w2 + b2 + attn      [4096,4096]x[4096,1024]
    tgemm_kernel<<<dim3(Dm/128, ROWS/128), 256>>>(mlp, w2, b2, attn,
                                                  out, ROWS, Dm, FCm, 0);
}

// round 4
// speedup vs baseline: 2.6435x; 1.7873x over previous
#include <cuda_runtime.h>
#include <cuda_fp16.h>
#include <math.h>
#include <stdint.h>

#define Dm   1024
#define Sm   2048
#define Bm   2
#define Hm   16
#define HDm  64
#define FCm  4096
#define ROWS (Bm*Sm)        /* 4096 */
#define EPSm 1e-5f

// Scratch (no cudaMalloc allowed)
__device__ float g_h1  [(size_t)ROWS*Dm];
__device__ float g_qkv [(size_t)ROWS*3*Dm];
__device__ float g_attn[(size_t)ROWS*Dm];
__device__ float g_h2  [(size_t)ROWS*Dm];
__device__ float g_mlp [(size_t)ROWS*FCm];

// ---------------------------------------------------------------------------
// LayerNorm (unchanged)
// ---------------------------------------------------------------------------
__global__ __launch_bounds__(256) void ln_kernel(
    const float* __restrict__ x, const float* __restrict__ g,
    const float* __restrict__ b, float* __restrict__ y)
{
    int row = blockIdx.x;
    int t = threadIdx.x;
    const float* xr = x + (size_t)row * Dm;
    float v[4];
#pragma unroll
    for (int i = 0; i < 4; i++) v[i] = xr[t + i*256];

    __shared__ float red[8];
    float s = v[0] + v[1] + v[2] + v[3];
#pragma unroll
    for (int o = 16; o > 0; o >>= 1) s += __shfl_xor_sync(0xffffffffu, s, o);
    if ((t & 31) == 0) red[t >> 5] = s;
    __syncthreads();
    float mu = (red[0]+red[1]+red[2]+red[3]+red[4]+red[5]+red[6]+red[7]) * (1.0f / Dm);
    __syncthreads();
    float q = 0.f;
#pragma unroll
    for (int i = 0; i < 4; i++) { float d0 = v[i] - mu; q += d0*d0; }
#pragma unroll
    for (int o = 16; o > 0; o >>= 1) q += __shfl_xor_sync(0xffffffffu, q, o);
    if ((t & 31) == 0) red[t >> 5] = q;
    __syncthreads();
    float var = (red[0]+red[1]+red[2]+red[3]+red[4]+red[5]+red[6]+red[7]) * (1.0f / Dm);
    float rstd = rsqrtf(var + EPSm);

    float* yr = y + (size_t)row * Dm;
#pragma unroll
    for (int i = 0; i < 4; i++) {
        int c = t + i*256;
        yr[c] = (v[i] - mu) * rstd * g[c] + b[c];
    }
}

// ---------------------------------------------------------------------------
// TF32 tensor-core GEMM (unchanged from R2)
// ---------------------------------------------------------------------------
__device__ __forceinline__ uint32_t f2tf32(float x) {
    uint32_t r;
    asm("cvt.rna.tf32.f32 %0, %1;" : "=r"(r) : "f"(x));
    return r;
}

__device__ __forceinline__ void mma_tf32(float c[4],
    uint32_t a0, uint32_t a1, uint32_t a2, uint32_t a3,
    uint32_t b0, uint32_t b1)
{
    asm volatile(
        "mma.sync.aligned.m16n8k8.row.col.f32.tf32.tf32.f32 "
        "{%0,%1,%2,%3}, {%4,%5,%6,%7}, {%8,%9}, {%0,%1,%2,%3};"
        : "+f"(c[0]), "+f"(c[1]), "+f"(c[2]), "+f"(c[3])
        : "r"(a0), "r"(a1), "r"(a2), "r"(a3), "r"(b0), "r"(b1));
}

#define TSTRIDE 132

__global__ __launch_bounds__(256) void tgemm_kernel(
    const float* __restrict__ A, const float* __restrict__ B,
    const float* __restrict__ bias, const float* __restrict__ res,
    float* __restrict__ C, int M, int N, int K, int relu)
{
    __shared__ uint32_t As[32][TSTRIDE];
    __shared__ uint32_t Bs[32][TSTRIDE];

    int tid  = threadIdx.x;
    int wid  = tid >> 5;
    int lane = tid & 31;
    int grp  = lane >> 2;
    int thr  = lane & 3;
    int warp_m = (wid >> 2) * 64;
    int warp_n = (wid & 3) * 32;
    int row0 = blockIdx.y * 128;
    int col0 = blockIdx.x * 128;

    float acc[4][4][4];
#pragma unroll
    for (int mi = 0; mi < 4; mi++)
#pragma unroll
        for (int ni = 0; ni < 4; ni++)
#pragma unroll
            for (int f = 0; f < 4; f++) acc[mi][ni][f] = 0.f;

    for (int k0 = 0; k0 < K; k0 += 32) {
#pragma unroll
        for (int i = 0; i < 4; i++) {
            int fi = tid + i * 256;
            int r  = fi >> 3;
            int kq = (fi & 7) * 4;
            float4 a4 = *(const float4*)(A + (size_t)(row0 + r) * K + k0 + kq);
            As[kq + 0][r] = f2tf32(a4.x);
            As[kq + 1][r] = f2tf32(a4.y);
            As[kq + 2][r] = f2tf32(a4.z);
            As[kq + 3][r] = f2tf32(a4.w);
        }
#pragma unroll
        for (int i = 0; i < 4; i++) {
            int fi = tid + i * 256;
            int kr = fi >> 5;
            int nc = (fi & 31) * 4;
            float4 b4 = *(const float4*)(B + (size_t)(k0 + kr) * N + col0 + nc);
            uint4 u;
            u.x = f2tf32(b4.x); u.y = f2tf32(b4.y);
            u.z = f2tf32(b4.z); u.w = f2tf32(b4.w);
            *(uint4*)&Bs[kr][nc] = u;
        }
        __syncthreads();

#pragma unroll
        for (int k8 = 0; k8 < 32; k8 += 8) {
            uint32_t af[4][4], bf[4][2];
#pragma unroll
            for (int mi = 0; mi < 4; mi++) {
                int m = warp_m + mi * 16;
                af[mi][0] = As[k8 + thr    ][m + grp    ];
                af[mi][1] = As[k8 + thr    ][m + grp + 8];
                af[mi][2] = As[k8 + thr + 4][m + grp    ];
                af[mi][3] = As[k8 + thr + 4][m + grp + 8];
            }
#pragma unroll
            for (int ni = 0; ni < 4; ni++) {
                int n = warp_n + ni * 8;
                bf[ni][0] = Bs[k8 + thr    ][n + grp];
                bf[ni][1] = Bs[k8 + thr + 4][n + grp];
            }
#pragma unroll
            for (int mi = 0; mi < 4; mi++)
#pragma unroll
                for (int ni = 0; ni < 4; ni++)
                    mma_tf32(acc[mi][ni],
                             af[mi][0], af[mi][1], af[mi][2], af[mi][3],
                             bf[ni][0], bf[ni][1]);
        }
        __syncthreads();
    }

#pragma unroll
    for (int mi = 0; mi < 4; mi++) {
#pragma unroll
        for (int ni = 0; ni < 4; ni++) {
            int r = row0 + warp_m + mi * 16 + grp;
            int c = col0 + warp_n + ni * 8 + 2 * thr;
            float b0 = bias[c], b1 = bias[c + 1];
            float o0 = acc[mi][ni][0] + b0;
            float o1 = acc[mi][ni][1] + b1;
            float o2 = acc[mi][ni][2] + b0;
            float o3 = acc[mi][ni][3] + b1;
            if (relu) {
                o0 = fmaxf(o0, 0.f); o1 = fmaxf(o1, 0.f);
                o2 = fmaxf(o2, 0.f); o3 = fmaxf(o3, 0.f);
            }
            if (res) {
                const float2 r0 = *(const float2*)(res + (size_t)r * N + c);
                const float2 r1 = *(const float2*)(res + (size_t)(r + 8) * N + c);
                o0 += r0.x; o1 += r0.y; o2 += r1.x; o3 += r1.y;
            }
            *(float2*)(C + (size_t)r * N + c)       = make_float2(o0, o1);
            *(float2*)(C + (size_t)(r + 8) * N + c) = make_float2(o2, o3);
        }
    }
}

// ---------------------------------------------------------------------------
// Tensor-core flash attention (f16 mma, f32 accum).
// CTA = 128 q-rows of one (b,h). 8 warps x 16 rows. K-tile = 64 keys.
//  - scores: mma.m16n8k16.f16, Q pre-scaled by 0.125*log2(e) -> base-2 softmax
//  - exp:    ex2.approx.f16x2 (2 exps per MUFU op)
//  - PV:     mma.m16n8k16.f16, V padded with a ones-column at d=64 so the
//            softmax denominator accumulates in the same accumulator.
// ---------------------------------------------------------------------------
__device__ __forceinline__ void mma_f16(float c[4],
    uint32_t a0, uint32_t a1, uint32_t a2, uint32_t a3,
    uint32_t b0, uint32_t b1)
{
    asm volatile(
        "mma.sync.aligned.m16n8k16.row.col.f32.f16.f16.f32 "
        "{%0,%1,%2,%3}, {%4,%5,%6,%7}, {%8,%9}, {%0,%1,%2,%3};"
        : "+f"(c[0]), "+f"(c[1]), "+f"(c[2]), "+f"(c[3])
        : "r"(a0), "r"(a1), "r"(a2), "r"(a3), "r"(b0), "r"(b1));
}

__device__ __forceinline__ uint32_t packh2(float lo, float hi) {
    __half2 h = __floats2half2_rn(lo, hi);
    return *(uint32_t*)&h;
}

__device__ __forceinline__ uint32_t h2exp2(uint32_t x) {
    uint32_t r;
    asm("ex2.approx.f16x2 %0, %1;" : "=r"(r) : "r"(x));
    return r;
}

#define KS 66   /* K2 row stride (keys) */
#define VS 72   /* V2 row stride (dims incl. ones col) */
#define PS 36   /* P2 row stride (key pairs) */

__global__ __launch_bounds__(256) void fattn_kernel(
    const float* __restrict__ qkv, const float* __restrict__ x,
    float* __restrict__ attn)
{
    __shared__ uint32_t K2[32][KS];      // half2 pairs along d:  [d/2][key]
    __shared__ uint32_t V2[32][VS];      // half2 pairs along key:[key/2][d], d=64 is ones
    __shared__ uint32_t P2[8][16][PS];   // per-warp P tile [row][key/2]

    int h = blockIdx.y, b = blockIdx.z;
    int tid = threadIdx.x, wid = tid >> 5, lane = tid & 31;
    int grp = lane >> 2, thr = lane & 3;

    int row_g  = b * Sm + blockIdx.x * 128 + wid * 16 + grp;
    int row_g8 = row_g + 8;

    const float QSCALE = 0.125f * 1.44269504088896f;  // scale * log2(e)

    // Q fragments (held in regs for all 32 key tiles)
    uint32_t qf[4][4];
#pragma unroll
    for (int kst = 0; kst < 4; kst++) {
        int d0 = kst * 16 + 2 * thr;
        int d2 = d0 + 8;
        const float* q0 = qkv + (size_t)row_g  * (3*Dm) + h * HDm;
        const float* q8 = qkv + (size_t)row_g8 * (3*Dm) + h * HDm;
        float2 a = *(const float2*)(q0 + d0);
        float2 c = *(const float2*)(q8 + d0);
        float2 e = *(const float2*)(q0 + d2);
        float2 f = *(const float2*)(q8 + d2);
        qf[kst][0] = packh2(a.x * QSCALE, a.y * QSCALE);
        qf[kst][1] = packh2(c.x * QSCALE, c.y * QSCALE);
        qf[kst][2] = packh2(e.x * QSCALE, e.y * QSCALE);
        qf[kst][3] = packh2(f.x * QSCALE, f.y * QSCALE);
    }

    // ones column (d=64) + zero pad (d=65..71), written once
    {
        int kp = tid >> 3;
        int c  = 64 + (tid & 7);
        V2[kp][c] = ((tid & 7) == 0) ? 0x3C003C00u : 0u;  // half2(1,1) : 0
    }

    float oa[9][4];
#pragma unroll
    for (int ni = 0; ni < 9; ni++)
#pragma unroll
        for (int f = 0; f < 4; f++) oa[ni][f] = 0.f;
    float m0 = -1e30f, m8 = -1e30f;

    for (int kk = 0; kk < Sm; kk += 64) {
        // ---- stage K (as half2 pairs along d) and V (pairs along key) ----
#pragma unroll
        for (int i = 0; i < 4; i++) {
            int fi  = tid + i * 256;          // 1024 float4 slots
            int key = fi >> 4;
            int dq  = (fi & 15) * 4;
            size_t base = (size_t)(b * Sm + kk + key) * (3*Dm) + h * HDm + dq;
            float4 kv = *(const float4*)(qkv + base + Dm);
            K2[(dq >> 1)    ][key] = packh2(kv.x, kv.y);
            K2[(dq >> 1) + 1][key] = packh2(kv.z, kv.w);
            float4 vv = *(const float4*)(qkv + base + 2*Dm);
            __half* vh = (__half*)&V2[key >> 1][dq];
            int p = key & 1;
            vh[p]     = __float2half_rn(vv.x);
            vh[p + 2] = __float2half_rn(vv.y);
            vh[p + 4] = __float2half_rn(vv.z);
            vh[p + 6] = __float2half_rn(vv.w);
        }
        __syncthreads();

        // ---- S = Q @ K^T (base-2 logits) ----
        float sa[8][4];
#pragma unroll
        for (int ni = 0; ni < 8; ni++)
#pragma unroll
            for (int f = 0; f < 4; f++) sa[ni][f] = 0.f;
#pragma unroll
        for (int kst = 0; kst < 4; kst++) {
#pragma unroll
            for (int ni = 0; ni < 8; ni++) {
                uint32_t b0 = K2[8*kst + thr    ][ni*8 + grp];
                uint32_t b1 = K2[8*kst + thr + 4][ni*8 + grp];
                mma_f16(sa[ni], qf[kst][0], qf[kst][1], qf[kst][2], qf[kst][3], b0, b1);
            }
        }

        // ---- online softmax ----
        float t0 = -1e30f, t8 = -1e30f;
#pragma unroll
        for (int ni = 0; ni < 8; ni++) {
            t0 = fmaxf(t0, fmaxf(sa[ni][0], sa[ni][1]));
            t8 = fmaxf(t8, fmaxf(sa[ni][2], sa[ni][3]));
        }
        t0 = fmaxf(t0, __shfl_xor_sync(0xffffffffu, t0, 1));
        t0 = fmaxf(t0, __shfl_xor_sync(0xffffffffu, t0, 2));
        t8 = fmaxf(t8, __shfl_xor_sync(0xffffffffu, t8, 1));
        t8 = fmaxf(t8, __shfl_xor_sync(0xffffffffu, t8, 2));
        float m0n = fmaxf(m0, t0);
        float m8n = fmaxf(m8, t8);
        float c0 = exp2f(m0 - m0n);
        float c8 = exp2f(m8 - m8n);
        m0 = m0n; m8 = m8n;
#pragma unroll
        for (int ni = 0; ni < 9; ni++) {
            oa[ni][0] *= c0; oa[ni][1] *= c0;
            oa[ni][2] *= c8; oa[ni][3] *= c8;
        }
#pragma unroll
        for (int ni = 0; ni < 8; ni++) {
            uint32_t e0 = h2exp2(packh2(sa[ni][0] - m0, sa[ni][1] - m0));
            uint32_t e8 = h2exp2(packh2(sa[ni][2] - m8, sa[ni][3] - m8));
            P2[wid][grp    ][ni*4 + thr] = e0;
            P2[wid][grp + 8][ni*4 + thr] = e8;
        }
        __syncwarp();

        // ---- O += P @ V  (col 64 accumulates sum(P)) ----
#pragma unroll
        for (int kst = 0; kst < 4; kst++) {
            uint32_t a0 = P2[wid][grp    ][8*kst + thr    ];
            uint32_t a1 = P2[wid][grp + 8][8*kst + thr    ];
            uint32_t a2 = P2[wid][grp    ][8*kst + thr + 4];
            uint32_t a3 = P2[wid][grp + 8][8*kst + thr + 4];
#pragma unroll
            for (int ni = 0; ni < 9; ni++) {
                uint32_t b0 = V2[8*kst + thr    ][ni*8 + grp];
                uint32_t b1 = V2[8*kst + thr + 4][ni*8 + grp];
                mma_f16(oa[ni], a0, a1, a2, a3, b0, b1);
            }
        }
        __syncthreads();
    }

    // ---- epilogue: normalize by row sum (col 64), add residual x ----
    int src = lane & ~3;
    float l0 = __shfl_sync(0xffffffffu, oa[8][0], src);
    float l8 = __shfl_sync(0xffffffffu, oa[8][2], src);
    float inv0 = 1.0f / l0;
    float inv8 = 1.0f / l8;
#pragma unroll
    for (int ni = 0; ni < 8; ni++) {
        int c = h * HDm + ni * 8 + 2 * thr;
        const float2 x0 = *(const float2*)(x + (size_t)row_g  * Dm + c);
        const float2 x8 = *(const float2*)(x + (size_t)row_g8 * Dm + c);
        float2 o0 = make_float2(oa[ni][0] * inv0 + x0.x, oa[ni][1] * inv0 + x0.y);
        float2 o8 = make_float2(oa[ni][2] * inv8 + x8.x, oa[ni][3] * inv8 + x8.y);
        *(float2*)(attn + (size_t)row_g  * Dm + c) = o0;
        *(float2*)(attn + (size_t)row_g8 * Dm + c) = o8;
    }
}

// ---------------------------------------------------------------------------
// Launch
// ---------------------------------------------------------------------------
extern "C" void kernel_launch(void* const* d_in, const int* in_sizes, int n_in,
                              void* d_out, int out_size)
{
    const float* x     = (const float*)d_in[0];
    const float* ln1_g = (const float*)d_in[1];
    const float* ln1_b = (const float*)d_in[2];
    const float* w_qkv = (const float*)d_in[3];
    const float* b_qkv = (const float*)d_in[4];
    const float* ln2_g = (const float*)d_in[5];
    const float* ln2_b = (const float*)d_in[6];
    const float* w1    = (const float*)d_in[7];
    const float* b1    = (const float*)d_in[8];
    const float* w2    = (const float*)d_in[9];
    const float* b2    = (const float*)d_in[10];
    float* out = (float*)d_out;

    float *h1, *qkv, *attn, *h2, *mlp;
    cudaGetSymbolAddress((void**)&h1,   g_h1);
    cudaGetSymbolAddress((void**)&qkv,  g_qkv);
    cudaGetSymbolAddress((void**)&attn, g_attn);
    cudaGetSymbolAddress((void**)&h2,   g_h2);
    cudaGetSymbolAddress((void**)&mlp,  g_mlp);

    // 1. LN1
    ln_kernel<<<ROWS, 256>>>(x, ln1_g, ln1_b, h1);
    // 2. QKV = h1 @ w_qkv + b_qkv
    tgemm_kernel<<<dim3(3*Dm/128, ROWS/128), 256>>>(h1, w_qkv, b_qkv, nullptr,
                                                    qkv, ROWS, 3*Dm, Dm, 0);
    // 3. attention + residual (tensor-core flash)
    fattn_kernel<<<dim3(Sm/128, Hm, Bm), 256>>>(qkv, x, attn);
    // 4. LN2
    ln_kernel<<<ROWS, 256>>>(attn, ln2_g, ln2_b, h2);
    // 5. m = relu(h2 @ w1 + b1)
    tgemm_kernel<<<dim3(FCm/128, ROWS/128), 256>>>(h2, w1, b1, nullptr,
                                                   mlp, ROWS, FCm, Dm, 1);
    // 6. out = m @ w2 + b2 + attn
    tgemm_kernel<<<dim3(Dm/128, ROWS/128), 256>>>(mlp, w2, b2, attn,
                                                  out, ROWS, Dm, FCm, 0);
}

// round 5
// speedup vs baseline: 4.9451x; 1.8707x over previous
#include <cuda_runtime.h>
#include <cuda_fp16.h>
#include <math.h>
#include <stdint.h>

#define Dm   1024
#define Sm   2048
#define Bm   2
#define Hm   16
#define HDm  64
#define FCm  4096
#define ROWS (Bm*Sm)        /* 4096 */
#define EPSm 1e-5f

// Scratch (no cudaMalloc allowed)
__device__ float g_h1  [(size_t)ROWS*Dm];
__device__ float g_qkv [(size_t)ROWS*3*Dm];
__device__ float g_attn[(size_t)ROWS*Dm];
__device__ float g_h2  [(size_t)ROWS*Dm];
__device__ float g_mlp [(size_t)ROWS*FCm];

// ---------------------------------------------------------------------------
// LayerNorm (unchanged)
// ---------------------------------------------------------------------------
__global__ __launch_bounds__(256) void ln_kernel(
    const float* __restrict__ x, const float* __restrict__ g,
    const float* __restrict__ b, float* __restrict__ y)
{
    int row = blockIdx.x;
    int t = threadIdx.x;
    const float* xr = x + (size_t)row * Dm;
    float v[4];
#pragma unroll
    for (int i = 0; i < 4; i++) v[i] = xr[t + i*256];

    __shared__ float red[8];
    float s = v[0] + v[1] + v[2] + v[3];
#pragma unroll
    for (int o = 16; o > 0; o >>= 1) s += __shfl_xor_sync(0xffffffffu, s, o);
    if ((t & 31) == 0) red[t >> 5] = s;
    __syncthreads();
    float mu = (red[0]+red[1]+red[2]+red[3]+red[4]+red[5]+red[6]+red[7]) * (1.0f / Dm);
    __syncthreads();
    float q = 0.f;
#pragma unroll
    for (int i = 0; i < 4; i++) { float d0 = v[i] - mu; q += d0*d0; }
#pragma unroll
    for (int o = 16; o > 0; o >>= 1) q += __shfl_xor_sync(0xffffffffu, q, o);
    if ((t & 31) == 0) red[t >> 5] = q;
    __syncthreads();
    float var = (red[0]+red[1]+red[2]+red[3]+red[4]+red[5]+red[6]+red[7]) * (1.0f / Dm);
    float rstd = rsqrtf(var + EPSm);

    float* yr = y + (size_t)row * Dm;
#pragma unroll
    for (int i = 0; i < 4; i++) {
        int c = t + i*256;
        yr[c] = (v[i] - mu) * rstd * g[c] + b[c];
    }
}

// ---------------------------------------------------------------------------
// f16 tensor-core GEMM (f32 accumulate): C = A@B + bias (+relu) (+res)
// Block 128x128x32, 256 threads (8 warps), warp tile 64x32,
// mma.sync.aligned.m16n8k16.row.col.f32.f16.f16.f32
// smem: As[k/2][m], Bs[k/2][n] as half2 packed along k, stride 132 words.
// Register prefetch pipeline: next tile's LDGs issue before current compute.
// ---------------------------------------------------------------------------
__device__ __forceinline__ uint32_t packh2(float lo, float hi) {
    __half2 h = __floats2half2_rn(lo, hi);
    return *(uint32_t*)&h;
}

__device__ __forceinline__ void mma_f16(float c[4],
    uint32_t a0, uint32_t a1, uint32_t a2, uint32_t a3,
    uint32_t b0, uint32_t b1)
{
    asm volatile(
        "mma.sync.aligned.m16n8k16.row.col.f32.f16.f16.f32 "
        "{%0,%1,%2,%3}, {%4,%5,%6,%7}, {%8,%9}, {%0,%1,%2,%3};"
        : "+f"(c[0]), "+f"(c[1]), "+f"(c[2]), "+f"(c[3])
        : "r"(a0), "r"(a1), "r"(a2), "r"(a3), "r"(b0), "r"(b1));
}

#define TSTRIDE 132

__global__ __launch_bounds__(256) void hgemm_kernel(
    const float* __restrict__ A, const float* __restrict__ B,
    const float* __restrict__ bias, const float* __restrict__ res,
    float* __restrict__ C, int M, int N, int K, int relu)
{
    __shared__ uint32_t As[16][TSTRIDE];   // [k/2][m]
    __shared__ uint32_t Bs[16][TSTRIDE];   // [k/2][n]

    int tid  = threadIdx.x;
    int wid  = tid >> 5;
    int lane = tid & 31;
    int grp  = lane >> 2;
    int thr  = lane & 3;
    int warp_m = (wid >> 2) * 64;
    int warp_n = (wid & 3) * 32;
    int row0 = blockIdx.y * 128;
    int col0 = blockIdx.x * 128;

    // A-load indices: 1024 float4 slots, 4 per thread
    int ar = tid >> 3;             // 0..31 base row (advances +32 per i... no: fi>>3)
    // B-load indices: 512 row-pair slots, 2 per thread
    float4 pa[4];
    float4 pb0[2], pb1[2];

    const float* Abase = A + (size_t)row0 * K;
    const float* Bbase = B + col0;

#define LDG_TILE(k0)                                                          \
    {                                                                         \
        _Pragma("unroll")                                                     \
        for (int i = 0; i < 4; i++) {                                         \
            int fi = tid + i * 256;                                           \
            int r  = fi >> 3;                                                 \
            int kq = (fi & 7) * 4;                                            \
            pa[i] = *(const float4*)(Abase + (size_t)r * K + (k0) + kq);      \
        }                                                                     \
        _Pragma("unroll")                                                     \
        for (int i = 0; i < 2; i++) {                                         \
            int fi = tid + i * 256;                                           \
            int kp = fi >> 5;                                                 \
            int nc = (fi & 31) * 4;                                           \
            const float* bp = Bbase + (size_t)((k0) + 2*kp) * N + nc;         \
            pb0[i] = *(const float4*)bp;                                      \
            pb1[i] = *(const float4*)(bp + N);                                \
        }                                                                     \
    }

#define STS_TILE()                                                            \
    {                                                                         \
        _Pragma("unroll")                                                     \
        for (int i = 0; i < 4; i++) {                                         \
            int fi = tid + i * 256;                                           \
            int r  = fi >> 3;                                                 \
            int kq = (fi & 7) * 4;                                            \
            As[(kq >> 1)    ][r] = packh2(pa[i].x, pa[i].y);                  \
            As[(kq >> 1) + 1][r] = packh2(pa[i].z, pa[i].w);                  \
        }                                                                     \
        _Pragma("unroll")                                                     \
        for (int i = 0; i < 2; i++) {                                         \
            int fi = tid + i * 256;                                           \
            int kp = fi >> 5;                                                 \
            int nc = (fi & 31) * 4;                                           \
            uint4 u;                                                          \
            u.x = packh2(pb0[i].x, pb1[i].x);                                 \
            u.y = packh2(pb0[i].y, pb1[i].y);                                 \
            u.z = packh2(pb0[i].z, pb1[i].z);                                 \
            u.w = packh2(pb0[i].w, pb1[i].w);                                 \
            *(uint4*)&Bs[kp][nc] = u;                                         \
        }                                                                     \
    }

    float acc[4][4][4];
#pragma unroll
    for (int mi = 0; mi < 4; mi++)
#pragma unroll
        for (int ni = 0; ni < 4; ni++)
#pragma unroll
            for (int f = 0; f < 4; f++) acc[mi][ni][f] = 0.f;

    LDG_TILE(0);

    for (int k0 = 0; k0 < K; k0 += 32) {
        STS_TILE();
        __syncthreads();
        if (k0 + 32 < K) LDG_TILE(k0 + 32);

#pragma unroll
        for (int kst = 0; kst < 2; kst++) {
            uint32_t af[4][4], bf[4][2];
#pragma unroll
            for (int mi = 0; mi < 4; mi++) {
                int m = warp_m + mi * 16;
                af[mi][0] = As[8*kst + thr    ][m + grp    ];
                af[mi][1] = As[8*kst + thr    ][m + grp + 8];
                af[mi][2] = As[8*kst + thr + 4][m + grp    ];
                af[mi][3] = As[8*kst + thr + 4][m + grp + 8];
            }
#pragma unroll
            for (int ni = 0; ni < 4; ni++) {
                int n = warp_n + ni * 8;
                bf[ni][0] = Bs[8*kst + thr    ][n + grp];
                bf[ni][1] = Bs[8*kst + thr + 4][n + grp];
            }
#pragma unroll
            for (int mi = 0; mi < 4; mi++)
#pragma unroll
                for (int ni = 0; ni < 4; ni++)
                    mma_f16(acc[mi][ni],
                            af[mi][0], af[mi][1], af[mi][2], af[mi][3],
                            bf[ni][0], bf[ni][1]);
        }
        __syncthreads();
    }

#pragma unroll
    for (int mi = 0; mi < 4; mi++) {
#pragma unroll
        for (int ni = 0; ni < 4; ni++) {
            int r = row0 + warp_m + mi * 16 + grp;
            int c = col0 + warp_n + ni * 8 + 2 * thr;
            float b0 = bias[c], b1 = bias[c + 1];
            float o0 = acc[mi][ni][0] + b0;
            float o1 = acc[mi][ni][1] + b1;
            float o2 = acc[mi][ni][2] + b0;
            float o3 = acc[mi][ni][3] + b1;
            if (relu) {
                o0 = fmaxf(o0, 0.f); o1 = fmaxf(o1, 0.f);
                o2 = fmaxf(o2, 0.f); o3 = fmaxf(o3, 0.f);
            }
            if (res) {
                const float2 r0 = *(const float2*)(res + (size_t)r * N + c);
                const float2 r1 = *(const float2*)(res + (size_t)(r + 8) * N + c);
                o0 += r0.x; o1 += r0.y; o2 += r1.x; o3 += r1.y;
            }
            *(float2*)(C + (size_t)r * N + c)       = make_float2(o0, o1);
            *(float2*)(C + (size_t)(r + 8) * N + c) = make_float2(o2, o3);
        }
    }
}

// ---------------------------------------------------------------------------
// Tensor-core flash attention (unchanged from R3)
// ---------------------------------------------------------------------------
__device__ __forceinline__ uint32_t h2exp2(uint32_t x) {
    uint32_t r;
    asm("ex2.approx.f16x2 %0, %1;" : "=r"(r) : "r"(x));
    return r;
}

#define KS 66
#define VS 72
#define PS 36

__global__ __launch_bounds__(256) void fattn_kernel(
    const float* __restrict__ qkv, const float* __restrict__ x,
    float* __restrict__ attn)
{
    __shared__ uint32_t K2[32][KS];
    __shared__ uint32_t V2[32][VS];
    __shared__ uint32_t P2[8][16][PS];

    int h = blockIdx.y, b = blockIdx.z;
    int tid = threadIdx.x, wid = tid >> 5, lane = tid & 31;
    int grp = lane >> 2, thr = lane & 3;

    int row_g  = b * Sm + blockIdx.x * 128 + wid * 16 + grp;
    int row_g8 = row_g + 8;

    const float QSCALE = 0.125f * 1.44269504088896f;

    uint32_t qf[4][4];
#pragma unroll
    for (int kst = 0; kst < 4; kst++) {
        int d0 = kst * 16 + 2 * thr;
        int d2 = d0 + 8;
        const float* q0 = qkv + (size_t)row_g  * (3*Dm) + h * HDm;
        const float* q8 = qkv + (size_t)row_g8 * (3*Dm) + h * HDm;
        float2 a = *(const float2*)(q0 + d0);
        float2 c = *(const float2*)(q8 + d0);
        float2 e = *(const float2*)(q0 + d2);
        float2 f = *(const float2*)(q8 + d2);
        qf[kst][0] = packh2(a.x * QSCALE, a.y * QSCALE);
        qf[kst][1] = packh2(c.x * QSCALE, c.y * QSCALE);
        qf[kst][2] = packh2(e.x * QSCALE, e.y * QSCALE);
        qf[kst][3] = packh2(f.x * QSCALE, f.y * QSCALE);
    }

    {
        int kp = tid >> 3;
        int c  = 64 + (tid & 7);
        V2[kp][c] = ((tid & 7) == 0) ? 0x3C003C00u : 0u;
    }

    float oa[9][4];
#pragma unroll
    for (int ni = 0; ni < 9; ni++)
#pragma unroll
        for (int f = 0; f < 4; f++) oa[ni][f] = 0.f;
    float m0 = -1e30f, m8 = -1e30f;

    for (int kk = 0; kk < Sm; kk += 64) {
#pragma unroll
        for (int i = 0; i < 4; i++) {
            int fi  = tid + i * 256;
            int key = fi >> 4;
            int dq  = (fi & 15) * 4;
            size_t base = (size_t)(b * Sm + kk + key) * (3*Dm) + h * HDm + dq;
            float4 kv = *(const float4*)(qkv + base + Dm);
            K2[(dq >> 1)    ][key] = packh2(kv.x, kv.y);
            K2[(dq >> 1) + 1][key] = packh2(kv.z, kv.w);
            float4 vv = *(const float4*)(qkv + base + 2*Dm);
            __half* vh = (__half*)&V2[key >> 1][dq];
            int p = key & 1;
            vh[p]     = __float2half_rn(vv.x);
            vh[p + 2] = __float2half_rn(vv.y);
            vh[p + 4] = __float2half_rn(vv.z);
            vh[p + 6] = __float2half_rn(vv.w);
        }
        __syncthreads();

        float sa[8][4];
#pragma unroll
        for (int ni = 0; ni < 8; ni++)
#pragma unroll
            for (int f = 0; f < 4; f++) sa[ni][f] = 0.f;
#pragma unroll
        for (int kst = 0; kst < 4; kst++) {
#pragma unroll
            for (int ni = 0; ni < 8; ni++) {
                uint32_t b0 = K2[8*kst + thr    ][ni*8 + grp];
                uint32_t b1 = K2[8*kst + thr + 4][ni*8 + grp];
                mma_f16(sa[ni], qf[kst][0], qf[kst][1], qf[kst][2], qf[kst][3], b0, b1);
            }
        }

        float t0 = -1e30f, t8 = -1e30f;
#pragma unroll
        for (int ni = 0; ni < 8; ni++) {
            t0 = fmaxf(t0, fmaxf(sa[ni][0], sa[ni][1]));
            t8 = fmaxf(t8, fmaxf(sa[ni][2], sa[ni][3]));
        }
        t0 = fmaxf(t0, __shfl_xor_sync(0xffffffffu, t0, 1));
        t0 = fmaxf(t0, __shfl_xor_sync(0xffffffffu, t0, 2));
        t8 = fmaxf(t8, __shfl_xor_sync(0xffffffffu, t8, 1));
        t8 = fmaxf(t8, __shfl_xor_sync(0xffffffffu, t8, 2));
        float m0n = fmaxf(m0, t0);
        float m8n = fmaxf(m8, t8);
        float c0 = exp2f(m0 - m0n);
        float c8 = exp2f(m8 - m8n);
        m0 = m0n; m8 = m8n;
#pragma unroll
        for (int ni = 0; ni < 9; ni++) {
            oa[ni][0] *= c0; oa[ni][1] *= c0;
            oa[ni][2] *= c8; oa[ni][3] *= c8;
        }
#pragma unroll
        for (int ni = 0; ni < 8; ni++) {
            uint32_t e0 = h2exp2(packh2(sa[ni][0] - m0, sa[ni][1] - m0));
            uint32_t e8 = h2exp2(packh2(sa[ni][2] - m8, sa[ni][3] - m8));
            P2[wid][grp    ][ni*4 + thr] = e0;
            P2[wid][grp + 8][ni*4 + thr] = e8;
        }
        __syncwarp();

#pragma unroll
        for (int kst = 0; kst < 4; kst++) {
            uint32_t a0 = P2[wid][grp    ][8*kst + thr    ];
            uint32_t a1 = P2[wid][grp + 8][8*kst + thr    ];
            uint32_t a2 = P2[wid][grp    ][8*kst + thr + 4];
            uint32_t a3 = P2[wid][grp + 8][8*kst + thr + 4];
#pragma unroll
            for (int ni = 0; ni < 9; ni++) {
                uint32_t b0 = V2[8*kst + thr    ][ni*8 + grp];
                uint32_t b1 = V2[8*kst + thr + 4][ni*8 + grp];
                mma_f16(oa[ni], a0, a1, a2, a3, b0, b1);
            }
        }
        __syncthreads();
    }

    int src = lane & ~3;
    float l0 = __shfl_sync(0xffffffffu, oa[8][0], src);
    float l8 = __shfl_sync(0xffffffffu, oa[8][2], src);
    float inv0 = 1.0f / l0;
    float inv8 = 1.0f / l8;
#pragma unroll
    for (int ni = 0; ni < 8; ni++) {
        int c = h * HDm + ni * 8 + 2 * thr;
        const float2 x0 = *(const float2*)(x + (size_t)row_g  * Dm + c);
        const float2 x8 = *(const float2*)(x + (size_t)row_g8 * Dm + c);
        float2 o0 = make_float2(oa[ni][0] * inv0 + x0.x, oa[ni][1] * inv0 + x0.y);
        float2 o8 = make_float2(oa[ni][2] * inv8 + x8.x, oa[ni][3] * inv8 + x8.y);
        *(float2*)(attn + (size_t)row_g  * Dm + c) = o0;
        *(float2*)(attn + (size_t)row_g8 * Dm + c) = o8;
    }
}

// ---------------------------------------------------------------------------
// Launch
// ---------------------------------------------------------------------------
extern "C" void kernel_launch(void* const* d_in, const int* in_sizes, int n_in,
                              void* d_out, int out_size)
{
    const float* x     = (const float*)d_in[0];
    const float* ln1_g = (const float*)d_in[1];
    const float* ln1_b = (const float*)d_in[2];
    const float* w_qkv = (const float*)d_in[3];
    const float* b_qkv = (const float*)d_in[4];
    const float* ln2_g = (const float*)d_in[5];
    const float* ln2_b = (const float*)d_in[6];
    const float* w1    = (const float*)d_in[7];
    const float* b1    = (const float*)d_in[8];
    const float* w2    = (const float*)d_in[9];
    const float* b2    = (const float*)d_in[10];
    float* out = (float*)d_out;

    float *h1, *qkv, *attn, *h2, *mlp;
    cudaGetSymbolAddress((void**)&h1,   g_h1);
    cudaGetSymbolAddress((void**)&qkv,  g_qkv);
    cudaGetSymbolAddress((void**)&attn, g_attn);
    cudaGetSymbolAddress((void**)&h2,   g_h2);
    cudaGetSymbolAddress((void**)&mlp,  g_mlp);

    // 1. LN1
    ln_kernel<<<ROWS, 256>>>(x, ln1_g, ln1_b, h1);
    // 2. QKV = h1 @ w_qkv + b_qkv
    hgemm_kernel<<<dim3(3*Dm/128, ROWS/128), 256>>>(h1, w_qkv, b_qkv, nullptr,
                                                    qkv, ROWS, 3*Dm, Dm, 0);
    // 3. attention + residual (tensor-core flash)
    fattn_kernel<<<dim3(Sm/128, Hm, Bm), 256>>>(qkv, x, attn);
    // 4. LN2
    ln_kernel<<<ROWS, 256>>>(attn, ln2_g, ln2_b, h2);
    // 5. m = relu(h2 @ w1 + b1)
    hgemm_kernel<<<dim3(FCm/128, ROWS/128), 256>>>(h2, w1, b1, nullptr,
                                                   mlp, ROWS, FCm, Dm, 1);
    // 6. out = m @ w2 + b2 + attn
    hgemm_kernel<<<dim3(Dm/128, ROWS/128), 256>>>(mlp, w2, b2, attn,
                                                  out, ROWS, Dm, FCm, 0);
}

// round 6
// speedup vs baseline: 5.1410x; 1.0396x over previous
#include <cuda_runtime.h>
#include <cuda_fp16.h>
#include <math.h>
#include <stdint.h>

#define Dm   1024
#define Sm   2048
#define Bm   2
#define Hm   16
#define HDm  64
#define FCm  4096
#define ROWS (Bm*Sm)        /* 4096 */
#define EPSm 1e-5f

// Scratch (no cudaMalloc allowed)
__device__ __half   g_h1h [(size_t)ROWS*Dm];         // 8 MB
__device__ __half   g_qkvh[(size_t)ROWS*3*Dm];       // 24 MB
__device__ float    g_attn[(size_t)ROWS*Dm];         // 16 MB
__device__ __half   g_h2h [(size_t)ROWS*Dm];         // 8 MB
__device__ __half   g_mlph[(size_t)ROWS*FCm];        // 32 MB
__device__ uint32_t g_wqkvp[(size_t)(Dm/2)*3*Dm];    // 6 MB
__device__ uint32_t g_w1p  [(size_t)(Dm/2)*FCm];     // 8 MB
__device__ uint32_t g_w2p  [(size_t)(FCm/2)*Dm];     // 8 MB

__device__ __forceinline__ uint32_t packh2(float lo, float hi) {
    __half2 h = __floats2half2_rn(lo, hi);
    return *(uint32_t*)&h;
}
__device__ __forceinline__ uint32_t hmul2u(uint32_t a, uint32_t b) {
    __half2 r = __hmul2(*(__half2*)&a, *(__half2*)&b);
    return *(uint32_t*)&r;
}

// ---------------------------------------------------------------------------
// Weight pack: w f32 [K,N] -> wp uint32 [K/2][N], wp[kp][n]=half2(w[2kp][n],w[2kp+1][n])
// ---------------------------------------------------------------------------
__global__ __launch_bounds__(256) void packw_kernel(
    const float* __restrict__ w, uint32_t* __restrict__ wp, int N)
{
    int n  = blockIdx.x * 256 + threadIdx.x;
    int kp = blockIdx.y;
    const float* src = w + (size_t)(2 * kp) * N + n;
    wp[(size_t)kp * N + n] = packh2(src[0], src[N]);
}

// ---------------------------------------------------------------------------
// LayerNorm, half output
// ---------------------------------------------------------------------------
__global__ __launch_bounds__(256) void ln_half_kernel(
    const float* __restrict__ x, const float* __restrict__ g,
    const float* __restrict__ b, __half* __restrict__ y)
{
    int row = blockIdx.x;
    int t = threadIdx.x;
    const float* xr = x + (size_t)row * Dm;
    float2 v[2];
    v[0] = *(const float2*)(xr + 2*t);
    v[1] = *(const float2*)(xr + 512 + 2*t);

    __shared__ float red[8];
    float s = v[0].x + v[0].y + v[1].x + v[1].y;
#pragma unroll
    for (int o = 16; o > 0; o >>= 1) s += __shfl_xor_sync(0xffffffffu, s, o);
    if ((t & 31) == 0) red[t >> 5] = s;
    __syncthreads();
    float mu = (red[0]+red[1]+red[2]+red[3]+red[4]+red[5]+red[6]+red[7]) * (1.0f / Dm);
    __syncthreads();
    float q = 0.f;
    {
        float d0 = v[0].x - mu, d1 = v[0].y - mu, d2 = v[1].x - mu, d3 = v[1].y - mu;
        q = d0*d0 + d1*d1 + d2*d2 + d3*d3;
    }
#pragma unroll
    for (int o = 16; o > 0; o >>= 1) q += __shfl_xor_sync(0xffffffffu, q, o);
    if ((t & 31) == 0) red[t >> 5] = q;
    __syncthreads();
    float var = (red[0]+red[1]+red[2]+red[3]+red[4]+red[5]+red[6]+red[7]) * (1.0f / Dm);
    float rstd = rsqrtf(var + EPSm);

    __half* yr = y + (size_t)row * Dm;
    {
        int c = 2*t;
        float2 gg = *(const float2*)(g + c);
        float2 bb = *(const float2*)(b + c);
        *(uint32_t*)(yr + c) = packh2((v[0].x - mu)*rstd*gg.x + bb.x,
                                      (v[0].y - mu)*rstd*gg.y + bb.y);
        c = 512 + 2*t;
        gg = *(const float2*)(g + c);
        bb = *(const float2*)(b + c);
        *(uint32_t*)(yr + c) = packh2((v[1].x - mu)*rstd*gg.x + bb.x,
                                      (v[1].y - mu)*rstd*gg.y + bb.y);
    }
}

// ---------------------------------------------------------------------------
// Half-in tensor-core GEMM, double-buffered smem, f32 accumulate.
// A: __half [M,K] row-major. Bp: uint32 [K/2][N] (half2 along k).
// Out: half (Ch) or float(+residual) (Cf).
// Block 128x128x32, 8 warps, warp tile 64x32, m16n8k16.
// ---------------------------------------------------------------------------
__device__ __forceinline__ void mma_f16(float c[4],
    uint32_t a0, uint32_t a1, uint32_t a2, uint32_t a3,
    uint32_t b0, uint32_t b1)
{
    asm volatile(
        "mma.sync.aligned.m16n8k16.row.col.f32.f16.f16.f32 "
        "{%0,%1,%2,%3}, {%4,%5,%6,%7}, {%8,%9}, {%0,%1,%2,%3};"
        : "+f"(c[0]), "+f"(c[1]), "+f"(c[2]), "+f"(c[3])
        : "r"(a0), "r"(a1), "r"(a2), "r"(a3), "r"(b0), "r"(b1));
}

#define TSTRIDE 132

__global__ __launch_bounds__(256) void hgemm_kernel(
    const __half* __restrict__ A, const uint32_t* __restrict__ Bp,
    const float* __restrict__ bias, const float* __restrict__ res,
    float* __restrict__ Cf, __half* __restrict__ Ch,
    int M, int N, int K, int relu)
{
    __shared__ uint32_t As[2][16][TSTRIDE];   // [stage][k/2][m]
    __shared__ uint32_t Bs[2][16][TSTRIDE];   // [stage][k/2][n]

    int tid  = threadIdx.x;
    int wid  = tid >> 5;
    int lane = tid & 31;
    int grp  = lane >> 2;
    int thr  = lane & 3;
    int warp_m = (wid >> 2) * 64;
    int warp_n = (wid & 3) * 32;
    int row0 = blockIdx.y * 128;
    int col0 = blockIdx.x * 128;

    const __half* Abase = A + (size_t)row0 * K;
    const uint32_t* Bbase = Bp + col0;

    uint4 pa[2], pb[2];

#define LDG_TILE(k0)                                                          \
    {                                                                         \
        _Pragma("unroll")                                                     \
        for (int i = 0; i < 2; i++) {                                         \
            int fi  = tid + i * 256;                                          \
            int r   = fi >> 2;                                                \
            int kq8 = (fi & 3) * 8;                                           \
            pa[i] = *(const uint4*)(Abase + (size_t)r * K + (k0) + kq8);      \
        }                                                                     \
        _Pragma("unroll")                                                     \
        for (int i = 0; i < 2; i++) {                                         \
            int fi = tid + i * 256;                                           \
            int kp = fi >> 5;                                                 \
            int nc = (fi & 31) * 4;                                           \
            pb[i] = *(const uint4*)(Bbase + (size_t)((k0)/2 + kp) * N + nc);  \
        }                                                                     \
    }

#define STS_TILE(st)                                                          \
    {                                                                         \
        _Pragma("unroll")                                                     \
        for (int i = 0; i < 2; i++) {                                         \
            int fi  = tid + i * 256;                                          \
            int r   = fi >> 2;                                                \
            int kp0 = (fi & 3) * 4;                                           \
            As[st][kp0 + 0][r] = pa[i].x;                                     \
            As[st][kp0 + 1][r] = pa[i].y;                                     \
            As[st][kp0 + 2][r] = pa[i].z;                                     \
            As[st][kp0 + 3][r] = pa[i].w;                                     \
        }                                                                     \
        _Pragma("unroll")                                                     \
        for (int i = 0; i < 2; i++) {                                         \
            int fi = tid + i * 256;                                           \
            int kp = fi >> 5;                                                 \
            int nc = (fi & 31) * 4;                                           \
            *(uint4*)&Bs[st][kp][nc] = pb[i];                                 \
        }                                                                     \
    }

    float acc[4][4][4];
#pragma unroll
    for (int mi = 0; mi < 4; mi++)
#pragma unroll
        for (int ni = 0; ni < 4; ni++)
#pragma unroll
            for (int f = 0; f < 4; f++) acc[mi][ni][f] = 0.f;

    LDG_TILE(0);
    STS_TILE(0);
    __syncthreads();

    int cur = 0;
    for (int k0 = 0; k0 < K; k0 += 32) {
        int more = (k0 + 32 < K);
        if (more) LDG_TILE(k0 + 32);

#pragma unroll
        for (int kst = 0; kst < 2; kst++) {
            uint32_t af[4][4], bf[4][2];
#pragma unroll
            for (int mi = 0; mi < 4; mi++) {
                int m = warp_m + mi * 16;
                af[mi][0] = As[cur][8*kst + thr    ][m + grp    ];
                af[mi][1] = As[cur][8*kst + thr    ][m + grp + 8];
                af[mi][2] = As[cur][8*kst + thr + 4][m + grp    ];
                af[mi][3] = As[cur][8*kst + thr + 4][m + grp + 8];
            }
#pragma unroll
            for (int ni = 0; ni < 4; ni++) {
                int n = warp_n + ni * 8;
                bf[ni][0] = Bs[cur][8*kst + thr    ][n + grp];
                bf[ni][1] = Bs[cur][8*kst + thr + 4][n + grp];
            }
#pragma unroll
            for (int mi = 0; mi < 4; mi++)
#pragma unroll
                for (int ni = 0; ni < 4; ni++)
                    mma_f16(acc[mi][ni],
                            af[mi][0], af[mi][1], af[mi][2], af[mi][3],
                            bf[ni][0], bf[ni][1]);
        }
        if (more) STS_TILE(cur ^ 1);
        __syncthreads();
        cur ^= 1;
    }

#pragma unroll
    for (int mi = 0; mi < 4; mi++) {
#pragma unroll
        for (int ni = 0; ni < 4; ni++) {
            int r = row0 + warp_m + mi * 16 + grp;
            int c = col0 + warp_n + ni * 8 + 2 * thr;
            float b0 = bias[c], b1 = bias[c + 1];
            float o0 = acc[mi][ni][0] + b0;
            float o1 = acc[mi][ni][1] + b1;
            float o2 = acc[mi][ni][2] + b0;
            float o3 = acc[mi][ni][3] + b1;
            if (relu) {
                o0 = fmaxf(o0, 0.f); o1 = fmaxf(o1, 0.f);
                o2 = fmaxf(o2, 0.f); o3 = fmaxf(o3, 0.f);
            }
            if (Ch) {
                *(uint32_t*)(Ch + (size_t)r * N + c)       = packh2(o0, o1);
                *(uint32_t*)(Ch + (size_t)(r + 8) * N + c) = packh2(o2, o3);
            } else {
                if (res) {
                    const float2 r0 = *(const float2*)(res + (size_t)r * N + c);
                    const float2 r1 = *(const float2*)(res + (size_t)(r + 8) * N + c);
                    o0 += r0.x; o1 += r0.y; o2 += r1.x; o3 += r1.y;
                }
                *(float2*)(Cf + (size_t)r * N + c)       = make_float2(o0, o1);
                *(float2*)(Cf + (size_t)(r + 8) * N + c) = make_float2(o2, o3);
            }
        }
    }
}

// ---------------------------------------------------------------------------
// Tensor-core flash attention, half qkv input, reg-prefetch K/V.
// ---------------------------------------------------------------------------
__device__ __forceinline__ uint32_t h2exp2(uint32_t x) {
    uint32_t r;
    asm("ex2.approx.f16x2 %0, %1;" : "=r"(r) : "r"(x));
    return r;
}

#define KS 66
#define VS 72
#define PS 36

__global__ __launch_bounds__(256) void fattn_kernel(
    const __half* __restrict__ qkv, const float* __restrict__ x,
    float* __restrict__ attn)
{
    __shared__ uint32_t K2[32][KS];      // [d/2][key]
    __shared__ uint32_t V2[32][VS];      // [key/2][d], col 64 = ones
    __shared__ uint32_t P2[8][16][PS];

    int h = blockIdx.y, b = blockIdx.z;
    int tid = threadIdx.x, wid = tid >> 5, lane = tid & 31;
    int grp = lane >> 2, thr = lane & 3;

    int row_g  = b * Sm + blockIdx.x * 128 + wid * 16 + grp;
    int row_g8 = row_g + 8;

    const float QSCALE = 0.125f * 1.44269504088896f;
    const uint32_t QS2 = packh2(QSCALE, QSCALE);

    uint32_t qf[4][4];
#pragma unroll
    for (int kst = 0; kst < 4; kst++) {
        int d0 = kst * 16 + 2 * thr;
        int d2 = d0 + 8;
        const __half* q0 = qkv + (size_t)row_g  * (3*Dm) + h * HDm;
        const __half* q8 = qkv + (size_t)row_g8 * (3*Dm) + h * HDm;
        qf[kst][0] = hmul2u(*(const uint32_t*)(q0 + d0), QS2);
        qf[kst][1] = hmul2u(*(const uint32_t*)(q8 + d0), QS2);
        qf[kst][2] = hmul2u(*(const uint32_t*)(q0 + d2), QS2);
        qf[kst][3] = hmul2u(*(const uint32_t*)(q8 + d2), QS2);
    }

    {   // ones column (d=64) + zero pad
        int kp = tid >> 3;
        int c  = 64 + (tid & 7);
        V2[kp][c] = ((tid & 7) == 0) ? 0x3C003C00u : 0u;
    }

    float oa[9][4];
#pragma unroll
    for (int ni = 0; ni < 9; ni++)
#pragma unroll
        for (int f = 0; f < 4; f++) oa[ni][f] = 0.f;
    float m0 = -1e30f, m8 = -1e30f;

    uint4 ku[2], vu[2];
#define LDG_KV(kk)                                                            \
    {                                                                         \
        _Pragma("unroll")                                                     \
        for (int i = 0; i < 2; i++) {                                         \
            int fi  = tid + i * 256;                                          \
            int key = fi >> 3;                                                \
            int dq  = (fi & 7) * 8;                                           \
            size_t base = (size_t)(b * Sm + (kk) + key) * (3*Dm) + h * HDm + dq; \
            ku[i] = *(const uint4*)(qkv + base + Dm);                         \
            vu[i] = *(const uint4*)(qkv + base + 2*Dm);                       \
        }                                                                     \
    }

    LDG_KV(0);

    for (int kk = 0; kk < Sm; kk += 64) {
        // ---- stage K/V from regs ----
#pragma unroll
        for (int i = 0; i < 2; i++) {
            int fi  = tid + i * 256;
            int key = fi >> 3;
            int dq  = (fi & 7) * 8;
            uint32_t* kw = (uint32_t*)&ku[i];
            K2[(dq >> 1) + 0][key] = kw[0];
            K2[(dq >> 1) + 1][key] = kw[1];
            K2[(dq >> 1) + 2][key] = kw[2];
            K2[(dq >> 1) + 3][key] = kw[3];
            __half* vh8 = (__half*)&vu[i];
            __half* dst = (__half*)&V2[key >> 1][dq];
            int p = key & 1;
#pragma unroll
            for (int j = 0; j < 8; j++) dst[2*j + p] = vh8[j];
        }
        __syncthreads();
        if (kk + 64 < Sm) LDG_KV(kk + 64);

        // ---- S = Q @ K^T ----
        float sa[8][4];
#pragma unroll
        for (int ni = 0; ni < 8; ni++)
#pragma unroll
            for (int f = 0; f < 4; f++) sa[ni][f] = 0.f;
#pragma unroll
        for (int kst = 0; kst < 4; kst++) {
#pragma unroll
            for (int ni = 0; ni < 8; ni++) {
                uint32_t b0 = K2[8*kst + thr    ][ni*8 + grp];
                uint32_t b1 = K2[8*kst + thr + 4][ni*8 + grp];
                mma_f16(sa[ni], qf[kst][0], qf[kst][1], qf[kst][2], qf[kst][3], b0, b1);
            }
        }

        // ---- online softmax ----
        float t0 = -1e30f, t8 = -1e30f;
#pragma unroll
        for (int ni = 0; ni < 8; ni++) {
            t0 = fmaxf(t0, fmaxf(sa[ni][0], sa[ni][1]));
            t8 = fmaxf(t8, fmaxf(sa[ni][2], sa[ni][3]));
        }
        t0 = fmaxf(t0, __shfl_xor_sync(0xffffffffu, t0, 1));
        t0 = fmaxf(t0, __shfl_xor_sync(0xffffffffu, t0, 2));
        t8 = fmaxf(t8, __shfl_xor_sync(0xffffffffu, t8, 1));
        t8 = fmaxf(t8, __shfl_xor_sync(0xffffffffu, t8, 2));
        float m0n = fmaxf(m0, t0);
        float m8n = fmaxf(m8, t8);
        float c0 = exp2f(m0 - m0n);
        float c8 = exp2f(m8 - m8n);
        m0 = m0n; m8 = m8n;
#pragma unroll
        for (int ni = 0; ni < 9; ni++) {
            oa[ni][0] *= c0; oa[ni][1] *= c0;
            oa[ni][2] *= c8; oa[ni][3] *= c8;
        }
#pragma unroll
        for (int ni = 0; ni < 8; ni++) {
            uint32_t e0 = h2exp2(packh2(sa[ni][0] - m0, sa[ni][1] - m0));
            uint32_t e8 = h2exp2(packh2(sa[ni][2] - m8, sa[ni][3] - m8));
            P2[wid][grp    ][ni*4 + thr] = e0;
            P2[wid][grp + 8][ni*4 + thr] = e8;
        }
        __syncwarp();

        // ---- O += P @ V ----
#pragma unroll
        for (int kst = 0; kst < 4; kst++) {
            uint32_t a0 = P2[wid][grp    ][8*kst + thr    ];
            uint32_t a1 = P2[wid][grp + 8][8*kst + thr    ];
            uint32_t a2 = P2[wid][grp    ][8*kst + thr + 4];
            uint32_t a3 = P2[wid][grp + 8][8*kst + thr + 4];
#pragma unroll
            for (int ni = 0; ni < 9; ni++) {
                uint32_t b0 = V2[8*kst + thr    ][ni*8 + grp];
                uint32_t b1 = V2[8*kst + thr + 4][ni*8 + grp];
                mma_f16(oa[ni], a0, a1, a2, a3, b0, b1);
            }
        }
        __syncthreads();
    }

    int src = lane & ~3;
    float l0 = __shfl_sync(0xffffffffu, oa[8][0], src);
    float l8 = __shfl_sync(0xffffffffu, oa[8][2], src);
    float inv0 = 1.0f / l0;
    float inv8 = 1.0f / l8;
#pragma unroll
    for (int ni = 0; ni < 8; ni++) {
        int c = h * HDm + ni * 8 + 2 * thr;
        const float2 x0 = *(const float2*)(x + (size_t)row_g  * Dm + c);
        const float2 x8 = *(const float2*)(x + (size_t)row_g8 * Dm + c);
        float2 o0 = make_float2(oa[ni][0] * inv0 + x0.x, oa[ni][1] * inv0 + x0.y);
        float2 o8 = make_float2(oa[ni][2] * inv8 + x8.x, oa[ni][3] * inv8 + x8.y);
        *(float2*)(attn + (size_t)row_g  * Dm + c) = o0;
        *(float2*)(attn + (size_t)row_g8 * Dm + c) = o8;
    }
}

// ---------------------------------------------------------------------------
// Launch
// ---------------------------------------------------------------------------
extern "C" void kernel_launch(void* const* d_in, const int* in_sizes, int n_in,
                              void* d_out, int out_size)
{
    const float* x     = (const float*)d_in[0];
    const float* ln1_g = (const float*)d_in[1];
    const float* ln1_b = (const float*)d_in[2];
    const float* w_qkv = (const float*)d_in[3];
    const float* b_qkv = (const float*)d_in[4];
    const float* ln2_g = (const float*)d_in[5];
    const float* ln2_b = (const float*)d_in[6];
    const float* w1    = (const float*)d_in[7];
    const float* b1    = (const float*)d_in[8];
    const float* w2    = (const float*)d_in[9];
    const float* b2    = (const float*)d_in[10];
    float* out = (float*)d_out;

    __half *h1h, *qkvh, *h2h, *mlph;
    float *attn;
    uint32_t *wqkvp, *w1p, *w2p;
    cudaGetSymbolAddress((void**)&h1h,   g_h1h);
    cudaGetSymbolAddress((void**)&qkvh,  g_qkvh);
    cudaGetSymbolAddress((void**)&attn,  g_attn);
    cudaGetSymbolAddress((void**)&h2h,   g_h2h);
    cudaGetSymbolAddress((void**)&mlph,  g_mlph);
    cudaGetSymbolAddress((void**)&wqkvp, g_wqkvp);
    cudaGetSymbolAddress((void**)&w1p,   g_w1p);
    cudaGetSymbolAddress((void**)&w2p,   g_w2p);

    // 0. pack weights to half2-along-k
    packw_kernel<<<dim3(3*Dm/256, Dm/2), 256>>>(w_qkv, wqkvp, 3*Dm);
    packw_kernel<<<dim3(FCm/256,  Dm/2), 256>>>(w1,    w1p,   FCm);
    packw_kernel<<<dim3(Dm/256,  FCm/2), 256>>>(w2,    w2p,   Dm);
    // 1. LN1 -> half
    ln_half_kernel<<<ROWS, 256>>>(x, ln1_g, ln1_b, h1h);
    // 2. QKV (half out)
    hgemm_kernel<<<dim3(3*Dm/128, ROWS/128), 256>>>(h1h, wqkvp, b_qkv, nullptr,
                                                    nullptr, qkvh, ROWS, 3*Dm, Dm, 0);
    // 3. attention + residual
    fattn_kernel<<<dim3(Sm/128, Hm, Bm), 256>>>(qkvh, x, attn);
    // 4. LN2 -> half
    ln_half_kernel<<<ROWS, 256>>>(attn, ln2_g, ln2_b, h2h);
    // 5. m = relu(h2 @ w1 + b1) (half out)
    hgemm_kernel<<<dim3(FCm/128, ROWS/128), 256>>>(h2h, w1p, b1, nullptr,
                                                   nullptr, mlph, ROWS, FCm, Dm, 1);
    // 6. out = m @ w2 + b2 + attn (f32 out)
    hgemm_kernel<<<dim3(Dm/128, ROWS/128), 256>>>(mlph, w2p, b2, attn,
                                                  out, nullptr, ROWS, Dm, FCm, 0);
}

// round 7
// speedup vs baseline: 9.3866x; 1.8258x over previous
#include <cuda_runtime.h>
#include <cuda_fp16.h>
#include <math.h>
#include <stdint.h>

#define Dm   1024
#define Sm   2048
#define Bm   2
#define Hm   16
#define HDm  64
#define FCm  4096
#define ROWS (Bm*Sm)        /* 4096 */
#define EPSm 1e-5f

// Scratch (no cudaMalloc allowed)
__device__ __half g_h1h [(size_t)ROWS*Dm];
__device__ __half g_qkvh[(size_t)ROWS*3*Dm];
__device__ float  g_attn[(size_t)ROWS*Dm];
__device__ __half g_h2h [(size_t)ROWS*Dm];
__device__ __half g_mlph[(size_t)ROWS*FCm];
__device__ __half g_wqkvT[(size_t)(3*Dm)*Dm];   // [N][K]
__device__ __half g_w1T  [(size_t)FCm*Dm];      // [N][K]
__device__ __half g_w2T  [(size_t)Dm*FCm];      // [N][K]

// ---------------------------------------------------------------------------
// PTX helpers
// ---------------------------------------------------------------------------
__device__ __forceinline__ uint32_t packh2(float lo, float hi) {
    __half2 h = __floats2half2_rn(lo, hi);
    return *(uint32_t*)&h;
}
__device__ __forceinline__ uint32_t hmul2u(uint32_t a, uint32_t b) {
    __half2 r = __hmul2(*(__half2*)&a, *(__half2*)&b);
    return *(uint32_t*)&r;
}
__device__ __forceinline__ uint32_t h2exp2(uint32_t x) {
    uint32_t r;
    asm("ex2.approx.f16x2 %0, %1;" : "=r"(r) : "r"(x));
    return r;
}
__device__ __forceinline__ uint32_t sm_u32(const void* p) {
    return (uint32_t)__cvta_generic_to_shared(p);
}
__device__ __forceinline__ void cp_async16(uint32_t s, const void* g) {
    asm volatile("cp.async.cg.shared.global [%0], [%1], 16;" :: "r"(s), "l"(g));
}
__device__ __forceinline__ void cp_commit() {
    asm volatile("cp.async.commit_group;");
}
template<int N> __device__ __forceinline__ void cp_wait() {
    asm volatile("cp.async.wait_group %0;" :: "n"(N));
}
__device__ __forceinline__ void ldsm4(uint32_t& r0, uint32_t& r1,
                                      uint32_t& r2, uint32_t& r3, uint32_t a) {
    asm volatile("ldmatrix.sync.aligned.m8n8.x4.shared.b16 {%0,%1,%2,%3}, [%4];"
                 : "=r"(r0), "=r"(r1), "=r"(r2), "=r"(r3) : "r"(a));
}
__device__ __forceinline__ void ldsm4t(uint32_t& r0, uint32_t& r1,
                                       uint32_t& r2, uint32_t& r3, uint32_t a) {
    asm volatile("ldmatrix.sync.aligned.m8n8.x4.trans.shared.b16 {%0,%1,%2,%3}, [%4];"
                 : "=r"(r0), "=r"(r1), "=r"(r2), "=r"(r3) : "r"(a));
}
__device__ __forceinline__ void mma_f16(float c[4],
    uint32_t a0, uint32_t a1, uint32_t a2, uint32_t a3,
    uint32_t b0, uint32_t b1)
{
    asm volatile(
        "mma.sync.aligned.m16n8k16.row.col.f32.f16.f16.f32 "
        "{%0,%1,%2,%3}, {%4,%5,%6,%7}, {%8,%9}, {%0,%1,%2,%3};"
        : "+f"(c[0]), "+f"(c[1]), "+f"(c[2]), "+f"(c[3])
        : "r"(a0), "r"(a1), "r"(a2), "r"(a3), "r"(b0), "r"(b1));
}

// ---------------------------------------------------------------------------
// Transpose-pack: w f32 [K][N] -> wt half [N][K]
// ---------------------------------------------------------------------------
__global__ __launch_bounds__(256) void packT_kernel(
    const float* __restrict__ w, __half* __restrict__ wt, int K, int N)
{
    __shared__ float tile[32][33];
    int n0 = blockIdx.x * 32, k0 = blockIdx.y * 32;
    int tx = threadIdx.x & 31, ty = threadIdx.x >> 5;   // ty 0..7
#pragma unroll
    for (int j = 0; j < 4; j++) {
        int k = ty + j * 8;
        tile[k][tx] = w[(size_t)(k0 + k) * N + n0 + tx];
    }
    __syncthreads();
#pragma unroll
    for (int j = 0; j < 4; j++) {
        int n = ty + j * 8;
        wt[(size_t)(n0 + n) * K + k0 + tx] = __float2half_rn(tile[tx][n]);
    }
}

// ---------------------------------------------------------------------------
// LayerNorm, half output
// ---------------------------------------------------------------------------
__global__ __launch_bounds__(256) void ln_half_kernel(
    const float* __restrict__ x, const float* __restrict__ g,
    const float* __restrict__ b, __half* __restrict__ y)
{
    int row = blockIdx.x;
    int t = threadIdx.x;
    const float* xr = x + (size_t)row * Dm;
    float2 v[2];
    v[0] = *(const float2*)(xr + 2*t);
    v[1] = *(const float2*)(xr + 512 + 2*t);

    __shared__ float red[8];
    float s = v[0].x + v[0].y + v[1].x + v[1].y;
#pragma unroll
    for (int o = 16; o > 0; o >>= 1) s += __shfl_xor_sync(0xffffffffu, s, o);
    if ((t & 31) == 0) red[t >> 5] = s;
    __syncthreads();
    float mu = (red[0]+red[1]+red[2]+red[3]+red[4]+red[5]+red[6]+red[7]) * (1.0f / Dm);
    __syncthreads();
    float q;
    {
        float d0 = v[0].x - mu, d1 = v[0].y - mu, d2 = v[1].x - mu, d3 = v[1].y - mu;
        q = d0*d0 + d1*d1 + d2*d2 + d3*d3;
    }
#pragma unroll
    for (int o = 16; o > 0; o >>= 1) q += __shfl_xor_sync(0xffffffffu, q, o);
    if ((t & 31) == 0) red[t >> 5] = q;
    __syncthreads();
    float var = (red[0]+red[1]+red[2]+red[3]+red[4]+red[5]+red[6]+red[7]) * (1.0f / Dm);
    float rstd = rsqrtf(var + EPSm);

    __half* yr = y + (size_t)row * Dm;
    {
        int c = 2*t;
        float2 gg = *(const float2*)(g + c);
        float2 bb = *(const float2*)(b + c);
        *(uint32_t*)(yr + c) = packh2((v[0].x - mu)*rstd*gg.x + bb.x,
                                      (v[0].y - mu)*rstd*gg.y + bb.y);
        c = 512 + 2*t;
        gg = *(const float2*)(g + c);
        bb = *(const float2*)(b + c);
        *(uint32_t*)(yr + c) = packh2((v[1].x - mu)*rstd*gg.x + bb.x,
                                      (v[1].y - mu)*rstd*gg.y + bb.y);
    }
}

// ---------------------------------------------------------------------------
// f16 GEMM: C[M,N] = A[M,K] @ Bt[N,K]^T + bias (+relu) (+res)
// Block 128x128, BK=64, 8 warps (warp 64x32). cp.async 2-stage, ldmatrix frags.
// smem (dynamic 64KB): per stage: A tile 128x64 half SW128, B tile 128x64 half.
// ---------------------------------------------------------------------------
__global__ __launch_bounds__(256) void hgemm_kernel(
    const __half* __restrict__ A, const __half* __restrict__ Bt,
    const float* __restrict__ bias, const float* __restrict__ res,
    float* __restrict__ Cf, __half* __restrict__ Ch,
    int M, int N, int K, int relu)
{
    extern __shared__ __half dsm[];
    uint32_t sbase = sm_u32(dsm);

    int tid = threadIdx.x, lane = tid & 31, wid = tid >> 5;
    int warp_m = (wid >> 2) * 64, warp_n = (wid & 3) * 32;
    int row0 = blockIdx.y * 128, col0 = blockIdx.x * 128;
    int tl = lane >> 3, lr = lane & 7;

    const __half* Ab = A  + (size_t)row0 * K;
    const __half* Bb = Bt + (size_t)col0 * K;

#define GLOAD(st, k0)                                                         \
    {                                                                         \
        _Pragma("unroll")                                                     \
        for (int i = 0; i < 4; i++) {                                         \
            int fi = tid + i * 256;                                           \
            int r = fi >> 3, c0 = fi & 7;                                     \
            uint32_t soff = (uint32_t)(st)*32768u + (uint32_t)r*128u          \
                          + (uint32_t)((c0 ^ (r & 7)) * 16);                  \
            cp_async16(sbase + soff, Ab + (size_t)r * K + (k0) + c0 * 8);     \
            cp_async16(sbase + soff + 16384u,                                 \
                       Bb + (size_t)r * K + (k0) + c0 * 8);                   \
        }                                                                     \
        cp_commit();                                                          \
    }

    float acc[4][4][4];
#pragma unroll
    for (int mi = 0; mi < 4; mi++)
#pragma unroll
        for (int ni = 0; ni < 4; ni++)
#pragma unroll
            for (int f = 0; f < 4; f++) acc[mi][ni][f] = 0.f;

    GLOAD(0, 0);

    int cur = 0;
    for (int k0 = 0; k0 < K; k0 += 64) {
        if (k0 + 64 < K) {
            GLOAD(cur ^ 1, k0 + 64);
            cp_wait<1>();
        } else {
            cp_wait<0>();
        }
        __syncthreads();

        uint32_t abase = sbase + (uint32_t)cur * 32768u;
        uint32_t bbase = abase + 16384u;
#pragma unroll
        for (int kst = 0; kst < 4; kst++) {
            uint32_t af[4][4], bf[4][2];
#pragma unroll
            for (int mi = 0; mi < 4; mi++) {
                int r = warp_m + mi * 16 + (tl & 1) * 8 + lr;
                int c = kst * 2 + (tl >> 1);
                ldsm4(af[mi][0], af[mi][1], af[mi][2], af[mi][3],
                      abase + (uint32_t)(r * 128 + ((c ^ (r & 7)) * 16)));
            }
#pragma unroll
            for (int nj = 0; nj < 2; nj++) {
                int n = warp_n + nj * 16 + (tl >> 1) * 8 + lr;
                int c = kst * 2 + (tl & 1);
                uint32_t r0, r1, r2, r3;
                ldsm4(r0, r1, r2, r3,
                      bbase + (uint32_t)(n * 128 + ((c ^ (n & 7)) * 16)));
                bf[2*nj][0] = r0; bf[2*nj][1] = r1;
                bf[2*nj+1][0] = r2; bf[2*nj+1][1] = r3;
            }
#pragma unroll
            for (int mi = 0; mi < 4; mi++)
#pragma unroll
                for (int ni = 0; ni < 4; ni++)
                    mma_f16(acc[mi][ni],
                            af[mi][0], af[mi][1], af[mi][2], af[mi][3],
                            bf[ni][0], bf[ni][1]);
        }
        __syncthreads();
        cur ^= 1;
    }

    int grp = lane >> 2, thr = lane & 3;
#pragma unroll
    for (int mi = 0; mi < 4; mi++) {
#pragma unroll
        for (int ni = 0; ni < 4; ni++) {
            int r = row0 + warp_m + mi * 16 + grp;
            int c = col0 + warp_n + ni * 8 + 2 * thr;
            float b0 = bias[c], b1 = bias[c + 1];
            float o0 = acc[mi][ni][0] + b0;
            float o1 = acc[mi][ni][1] + b1;
            float o2 = acc[mi][ni][2] + b0;
            float o3 = acc[mi][ni][3] + b1;
            if (relu) {
                o0 = fmaxf(o0, 0.f); o1 = fmaxf(o1, 0.f);
                o2 = fmaxf(o2, 0.f); o3 = fmaxf(o3, 0.f);
            }
            if (Ch) {
                *(uint32_t*)(Ch + (size_t)r * N + c)       = packh2(o0, o1);
                *(uint32_t*)(Ch + (size_t)(r + 8) * N + c) = packh2(o2, o3);
            } else {
                if (res) {
                    const float2 r0 = *(const float2*)(res + (size_t)r * N + c);
                    const float2 r1 = *(const float2*)(res + (size_t)(r + 8) * N + c);
                    o0 += r0.x; o1 += r0.y; o2 += r1.x; o3 += r1.y;
                }
                *(float2*)(Cf + (size_t)r * N + c)       = make_float2(o0, o1);
                *(float2*)(Cf + (size_t)(r + 8) * N + c) = make_float2(o2, o3);
            }
        }
    }
}

// ---------------------------------------------------------------------------
// Flash attention: cp.async K/V (natural [key][d] layout, SW128), ldmatrix
// fragments (K non-trans, V trans), P kept in registers, f32 row-sum.
// CTA = 128 q-rows of one (b,h), 8 warps x 16 rows, key tile 64, 2 stages.
// ---------------------------------------------------------------------------
__global__ __launch_bounds__(256) void fattn_kernel(
    const __half* __restrict__ qkv, const float* __restrict__ x,
    float* __restrict__ attn)
{
    __shared__ __half kv[2][2][64][64];   // [stage][K/V][key][d] swizzled, 32 KB
    uint32_t sbase = sm_u32(&kv[0][0][0][0]);

    int h = blockIdx.y, b = blockIdx.z;
    int tid = threadIdx.x, wid = tid >> 5, lane = tid & 31;
    int grp = lane >> 2, thr = lane & 3;
    int tl = lane >> 3, lr = lane & 7;

    int bS = b * Sm;
    int hoff = h * HDm;
    int row_g  = bS + blockIdx.x * 128 + wid * 16 + grp;
    int row_g8 = row_g + 8;

    const float QSCALE = 0.125f * 1.44269504088896f;
    const uint32_t QS2 = packh2(QSCALE, QSCALE);

    // Q fragments
    uint32_t qf[4][4];
#pragma unroll
    for (int kst = 0; kst < 4; kst++) {
        int d0 = kst * 16 + 2 * thr;
        const __half* q0 = qkv + (size_t)row_g  * (3*Dm) + hoff;
        const __half* q8 = qkv + (size_t)row_g8 * (3*Dm) + hoff;
        qf[kst][0] = hmul2u(*(const uint32_t*)(q0 + d0),     QS2);
        qf[kst][1] = hmul2u(*(const uint32_t*)(q8 + d0),     QS2);
        qf[kst][2] = hmul2u(*(const uint32_t*)(q0 + d0 + 8), QS2);
        qf[kst][3] = hmul2u(*(const uint32_t*)(q8 + d0 + 8), QS2);
    }

#define KVLOAD(st, kk)                                                        \
    {                                                                         \
        _Pragma("unroll")                                                     \
        for (int i = 0; i < 4; i++) {                                         \
            int fi = tid + i * 256;                                           \
            int sel = fi >> 9, r = (fi >> 3) & 63, c0 = fi & 7;               \
            const __half* g = qkv + (size_t)(bS + (kk) + r) * (3*Dm)          \
                            + hoff + c0 * 8 + Dm * (1 + sel);                 \
            uint32_t soff = (uint32_t)(st)*16384u + (uint32_t)sel*8192u       \
                          + (uint32_t)r*128u + (uint32_t)((c0 ^ (r & 7))*16); \
            cp_async16(sbase + soff, g);                                      \
        }                                                                     \
        cp_commit();                                                          \
    }

    float oa[8][4];
#pragma unroll
    for (int ni = 0; ni < 8; ni++)
#pragma unroll
        for (int f = 0; f < 4; f++) oa[ni][f] = 0.f;
    float m0 = -1e30f, m8 = -1e30f;
    float l0 = 0.f, l8 = 0.f;

    KVLOAD(0, 0);

    int cur = 0;
    for (int kk = 0; kk < Sm; kk += 64) {
        if (kk + 64 < Sm) {
            KVLOAD(cur ^ 1, kk + 64);
            cp_wait<1>();
        } else {
            cp_wait<0>();
        }
        __syncthreads();

        uint32_t kbase = sbase + (uint32_t)cur * 16384u;
        uint32_t vbase = kbase + 8192u;

        // ---- S = Q @ K^T ----
        float sa[8][4];
#pragma unroll
        for (int ni = 0; ni < 8; ni++)
#pragma unroll
            for (int f = 0; f < 4; f++) sa[ni][f] = 0.f;
#pragma unroll
        for (int kst = 0; kst < 4; kst++) {
            uint32_t bf[8][2];
#pragma unroll
            for (int g4 = 0; g4 < 4; g4++) {
                int n = g4 * 16 + (tl >> 1) * 8 + lr;
                int c = kst * 2 + (tl & 1);
                uint32_t r0, r1, r2, r3;
                ldsm4(r0, r1, r2, r3,
                      kbase + (uint32_t)(n * 128 + ((c ^ (n & 7)) * 16)));
                bf[2*g4][0] = r0; bf[2*g4][1] = r1;
                bf[2*g4+1][0] = r2; bf[2*g4+1][1] = r3;
            }
#pragma unroll
            for (int ni = 0; ni < 8; ni++)
                mma_f16(sa[ni], qf[kst][0], qf[kst][1], qf[kst][2], qf[kst][3],
                        bf[ni][0], bf[ni][1]);
        }

        // ---- online softmax (base-2), P in regs ----
        float t0 = -1e30f, t8 = -1e30f;
#pragma unroll
        for (int ni = 0; ni < 8; ni++) {
            t0 = fmaxf(t0, fmaxf(sa[ni][0], sa[ni][1]));
            t8 = fmaxf(t8, fmaxf(sa[ni][2], sa[ni][3]));
        }
        t0 = fmaxf(t0, __shfl_xor_sync(0xffffffffu, t0, 1));
        t0 = fmaxf(t0, __shfl_xor_sync(0xffffffffu, t0, 2));
        t8 = fmaxf(t8, __shfl_xor_sync(0xffffffffu, t8, 1));
        t8 = fmaxf(t8, __shfl_xor_sync(0xffffffffu, t8, 2));
        float m0n = fmaxf(m0, t0);
        float m8n = fmaxf(m8, t8);
        float c0 = exp2f(m0 - m0n);
        float c8 = exp2f(m8 - m8n);
        m0 = m0n; m8 = m8n;
        l0 *= c0; l8 *= c8;
#pragma unroll
        for (int ni = 0; ni < 8; ni++) {
            oa[ni][0] *= c0; oa[ni][1] *= c0;
            oa[ni][2] *= c8; oa[ni][3] *= c8;
        }
        uint32_t e0[8], e8[8];
#pragma unroll
        for (int ni = 0; ni < 8; ni++) {
            e0[ni] = h2exp2(packh2(sa[ni][0] - m0, sa[ni][1] - m0));
            e8[ni] = h2exp2(packh2(sa[ni][2] - m8, sa[ni][3] - m8));
            float2 f0 = __half22float2(*(__half2*)&e0[ni]);
            float2 f8 = __half22float2(*(__half2*)&e8[ni]);
            l0 += f0.x + f0.y;
            l8 += f8.x + f8.y;
        }

        // ---- O += P @ V (V^T frags via ldmatrix.trans) ----
#pragma unroll
        for (int kst = 0; kst < 4; kst++) {
            uint32_t a0 = e0[2*kst], a1 = e8[2*kst];
            uint32_t a2 = e0[2*kst+1], a3 = e8[2*kst+1];
            uint32_t bv[8][2];
#pragma unroll
            for (int j = 0; j < 4; j++) {
                int r = kst * 16 + (tl & 1) * 8 + lr;
                int c = j * 2 + (tl >> 1);
                uint32_t r0, r1, r2, r3;
                ldsm4t(r0, r1, r2, r3,
                       vbase + (uint32_t)(r * 128 + ((c ^ (r & 7)) * 16)));
                bv[2*j][0] = r0; bv[2*j][1] = r1;
                bv[2*j+1][0] = r2; bv[2*j+1][1] = r3;
            }
#pragma unroll
            for (int ni = 0; ni < 8; ni++)
                mma_f16(oa[ni], a0, a1, a2, a3, bv[ni][0], bv[ni][1]);
        }
        __syncthreads();
        cur ^= 1;
    }

    // ---- epilogue ----
    l0 += __shfl_xor_sync(0xffffffffu, l0, 1);
    l0 += __shfl_xor_sync(0xffffffffu, l0, 2);
    l8 += __shfl_xor_sync(0xffffffffu, l8, 1);
    l8 += __shfl_xor_sync(0xffffffffu, l8, 2);
    float inv0 = 1.0f / l0;
    float inv8 = 1.0f / l8;
#pragma unroll
    for (int ni = 0; ni < 8; ni++) {
        int c = hoff + ni * 8 + 2 * thr;
        const float2 x0 = *(const float2*)(x + (size_t)row_g  * Dm + c);
        const float2 x8 = *(const float2*)(x + (size_t)row_g8 * Dm + c);
        float2 o0 = make_float2(oa[ni][0] * inv0 + x0.x, oa[ni][1] * inv0 + x0.y);
        float2 o8 = make_float2(oa[ni][2] * inv8 + x8.x, oa[ni][3] * inv8 + x8.y);
        *(float2*)(attn + (size_t)row_g  * Dm + c) = o0;
        *(float2*)(attn + (size_t)row_g8 * Dm + c) = o8;
    }
}

// ---------------------------------------------------------------------------
// Launch
// ---------------------------------------------------------------------------
extern "C" void kernel_launch(void* const* d_in, const int* in_sizes, int n_in,
                              void* d_out, int out_size)
{
    const float* x     = (const float*)d_in[0];
    const float* ln1_g = (const float*)d_in[1];
    const float* ln1_b = (const float*)d_in[2];
    const float* w_qkv = (const float*)d_in[3];
    const float* b_qkv = (const float*)d_in[4];
    const float* ln2_g = (const float*)d_in[5];
    const float* ln2_b = (const float*)d_in[6];
    const float* w1    = (const float*)d_in[7];
    const float* b1    = (const float*)d_in[8];
    const float* w2    = (const float*)d_in[9];
    const float* b2    = (const float*)d_in[10];
    float* out = (float*)d_out;

    __half *h1h, *qkvh, *h2h, *mlph, *wqkvT, *w1T, *w2T;
    float *attn;
    cudaGetSymbolAddress((void**)&h1h,   g_h1h);
    cudaGetSymbolAddress((void**)&qkvh,  g_qkvh);
    cudaGetSymbolAddress((void**)&attn,  g_attn);
    cudaGetSymbolAddress((void**)&h2h,   g_h2h);
    cudaGetSymbolAddress((void**)&mlph,  g_mlph);
    cudaGetSymbolAddress((void**)&wqkvT, g_wqkvT);
    cudaGetSymbolAddress((void**)&w1T,   g_w1T);
    cudaGetSymbolAddress((void**)&w2T,   g_w2T);

    cudaFuncSetAttribute(hgemm_kernel,
                         cudaFuncAttributeMaxDynamicSharedMemorySize, 65536);

    // 0. transpose-pack weights to [N][K] half
    packT_kernel<<<dim3(3*Dm/32, Dm/32), 256>>>(w_qkv, wqkvT, Dm, 3*Dm);
    packT_kernel<<<dim3(FCm/32,  Dm/32), 256>>>(w1,    w1T,   Dm, FCm);
    packT_kernel<<<dim3(Dm/32,  FCm/32), 256>>>(w2,    w2T,   FCm, Dm);
    // 1. LN1 -> half
    ln_half_kernel<<<ROWS, 256>>>(x, ln1_g, ln1_b, h1h);
    // 2. QKV (half out)
    hgemm_kernel<<<dim3(3*Dm/128, ROWS/128), 256, 65536>>>(
        h1h, wqkvT, b_qkv, nullptr, nullptr, qkvh, ROWS, 3*Dm, Dm, 0);
    // 3. attention + residual
    fattn_kernel<<<dim3(Sm/128, Hm, Bm), 256>>>(qkvh, x, attn);
    // 4. LN2 -> half
    ln_half_kernel<<<ROWS, 256>>>(attn, ln2_g, ln2_b, h2h);
    // 5. m = relu(h2 @ w1 + b1) (half out)
    hgemm_kernel<<<dim3(FCm/128, ROWS/128), 256, 65536>>>(
        h2h, w1T, b1, nullptr, nullptr, mlph, ROWS, FCm, Dm, 1);
    // 6. out = m @ w2 + b2 + attn (f32 out)
    hgemm_kernel<<<dim3(Dm/128, ROWS/128), 256, 65536>>>(
        mlph, w2T, b2, attn, out, nullptr, ROWS, Dm, FCm, 0);
}